// round 2
// baseline (speedup 1.0000x reference)
#include <cuda_runtime.h>
#include <math.h>

#define H_   12
#define T_   512
#define D_   64
#define C_   768
#define B_   32
#define NQKV_ 2304
#define BT_  16384
#define QSCALE 0.125f

// ------------- device-global scratch (no runtime alloc allowed) -------------
__device__ __align__(16) float g_wqkvT[C_ * NQKV_];
__device__ __align__(16) float g_q[(size_t)B_*H_*T_*D_];
__device__ __align__(16) float g_k[(size_t)B_*H_*T_*D_];
__device__ __align__(16) float g_v[(size_t)B_*H_*T_*D_];
__device__ __align__(16) float g_o[(size_t)BT_*C_];
__device__ __align__(16) float g_wcomb[C_*C_];
__device__ __align__(16) float g_bcomb[C_];

// ------------------------------ prep kernels --------------------------------
__global__ void __launch_bounds__(256) k_transpose(const float* __restrict__ Wqkv) {
    int idx = blockIdx.x * 256 + threadIdx.x;
    if (idx >= C_ * NQKV_) return;
    int c = idx / NQKV_, n = idx % NQKV_;
    int h = n / 192, j = n % 192;
    g_wqkvT[idx] = Wqkv[((size_t)h*C_ + c)*192 + j];
}

__global__ void __launch_bounds__(256) k_bcomb(const float* __restrict__ bph,
                                               const float* __restrict__ Wproj,
                                               const float* __restrict__ bproj) {
    int c = blockIdx.x * 256 + threadIdx.x;
    if (c >= C_) return;
    float acc = bproj[c];
    for (int r = 0; r < H_*C_; ++r)
        acc = fmaf(bph[r], Wproj[(size_t)r*C_ + c], acc);
    g_bcomb[c] = acc;
}

// --------------------------- tiled SGEMM template ---------------------------
// C[M,N] = A[M,K] @ B[K,N]; blockIdx.z batches via strides.
// EPI==0: C += bias[n] (bias may be null). EPI==1: QKV scatter epilogue.
template<int BM,int BN,int BK,int TM,int TN,int EPI>
__global__ void __launch_bounds__(256) sgemm_k(
    const float* __restrict__ A, const float* __restrict__ Bm,
    float* __restrict__ Cm, const float* __restrict__ bias,
    int M, int N, int K, long long sA, long long sB, long long sC)
{
    constexpr int TX = BN/TN, TY = BM/TM;
    static_assert(TX*TY == 256, "need 256 threads");
    __shared__ float As[BK][BM+4];
    __shared__ float Bs[BK][BN+4];

    const float* Ab = A  + (size_t)blockIdx.z * sA;
    const float* Bb = Bm + (size_t)blockIdx.z * sB;
    float*       Cb = Cm + (size_t)blockIdx.z * sC;

    const int tid = threadIdx.x;
    const int tx = tid % TX, ty = tid / TX;
    const int m0 = blockIdx.x * BM, n0 = blockIdx.y * BN;

    float acc[TM][TN] = {};
    constexpr int KB4   = BK/4;
    constexpr int A_PER = BM*KB4/256;
    constexpr int B_PER = BK*(BN/4)/256;

    for (int kt = 0; kt < K; kt += BK) {
        #pragma unroll
        for (int r = 0; r < A_PER; ++r) {
            int f4 = tid + r*256;
            int m  = f4 / KB4;
            int kq = (f4 % KB4) * 4;
            float4 v = *(const float4*)(Ab + (size_t)(m0+m)*K + kt + kq);
            As[kq+0][m] = v.x; As[kq+1][m] = v.y;
            As[kq+2][m] = v.z; As[kq+3][m] = v.w;
        }
        #pragma unroll
        for (int r = 0; r < B_PER; ++r) {
            int f4 = tid + r*256;
            int kk = f4 / (BN/4);
            int nn = (f4 % (BN/4)) * 4;
            *(float4*)&Bs[kk][nn] = *(const float4*)(Bb + (size_t)(kt+kk)*N + n0 + nn);
        }
        __syncthreads();
        #pragma unroll
        for (int k = 0; k < BK; ++k) {
            float a[TM], b[TN];
            #pragma unroll
            for (int i = 0; i < TM; i += 4)
                *(float4*)(a+i) = *(const float4*)&As[k][ty*TM + i];
            #pragma unroll
            for (int j = 0; j < TN; j += 4)
                *(float4*)(b+j) = *(const float4*)&Bs[k][tx*TN + j];
            #pragma unroll
            for (int i = 0; i < TM; ++i)
                #pragma unroll
                for (int j = 0; j < TN; ++j)
                    acc[i][j] = fmaf(a[i], b[j], acc[i][j]);
        }
        __syncthreads();
    }

    if (EPI == 0) {
        #pragma unroll
        for (int i = 0; i < TM; ++i) {
            int m = m0 + ty*TM + i;
            #pragma unroll
            for (int j = 0; j < TN; ++j) {
                int n = n0 + tx*TN + j;
                float bv = bias ? bias[n] : 0.0f;
                Cb[(size_t)m*N + n] = acc[i][j] + bv;
            }
        }
    } else {
        #pragma unroll
        for (int i = 0; i < TM; ++i) {
            int m = m0 + ty*TM + i;
            int b_ = m / T_, t = m % T_;
            #pragma unroll
            for (int j = 0; j < TN; ++j) {
                int n = n0 + tx*TN + j;
                int h = n / 192, r = n % 192;
                float v = acc[i][j] + bias[n];
                size_t base = (((size_t)b_*H_ + h)*T_ + t)*64;
                if (r < 64)       g_q[base + r]        = v * QSCALE;
                else if (r < 128) g_k[base + (r-64)]   = v;
                else              g_v[base + (r-128)]  = v;
            }
        }
    }
}

// ----------------------------- fused attention ------------------------------
// One CTA: (b, h, 64-row q tile). S[64][512] in smem; softmax; probs out; PV.
__global__ void __launch_bounds__(256) attn_k(float* __restrict__ probs)
{
    extern __shared__ float sm[];
    float (*S)[512] = (float(*)[512])sm;                       // 64*512
    float (*Qs)[68] = (float(*)[68])(sm + 64*512);             // 64*68
    float (*KV)[68] = (float(*)[68])(sm + 64*512 + 64*68);     // 64*68

    const int tid = threadIdx.x;
    const int t0 = blockIdx.x * 64;
    const int h = blockIdx.y, b = blockIdx.z;
    const size_t qbase = (((size_t)b*H_ + h)*T_ + t0)*64;
    const size_t kvbase = (((size_t)b*H_ + h)*T_)*64;
    const int tx = tid % 16, ty = tid / 16;

    // load Q tile [64][64]
    #pragma unroll
    for (int r = 0; r < 4; ++r) {
        int f4 = tid + r*256;
        int row = f4 >> 4, col = (f4 & 15) * 4;
        *(float4*)&Qs[row][col] = *(const float4*)&g_q[qbase + (size_t)row*64 + col];
    }

    // ---- S = Q @ K^T ----
    for (int st = 0; st < 8; ++st) {
        __syncthreads();
        #pragma unroll
        for (int r = 0; r < 4; ++r) {
            int f4 = tid + r*256;
            int row = f4 >> 4, col = (f4 & 15) * 4;
            float4 v = *(const float4*)&g_k[kvbase + (size_t)(st*64+row)*64 + col];
            KV[col+0][row] = v.x; KV[col+1][row] = v.y;
            KV[col+2][row] = v.z; KV[col+3][row] = v.w;   // transposed: KV[d][s]
        }
        __syncthreads();
        float acc[4][4] = {};
        #pragma unroll 8
        for (int d = 0; d < 64; ++d) {
            float4 b4 = *(float4*)&KV[d][tx*4];
            float bb[4] = {b4.x, b4.y, b4.z, b4.w};
            float a[4];
            #pragma unroll
            for (int i = 0; i < 4; ++i) a[i] = Qs[ty*4+i][d];
            #pragma unroll
            for (int i = 0; i < 4; ++i)
                #pragma unroll
                for (int j = 0; j < 4; ++j)
                    acc[i][j] = fmaf(a[i], bb[j], acc[i][j]);
        }
        #pragma unroll
        for (int i = 0; i < 4; ++i)
            #pragma unroll
            for (int j = 0; j < 4; ++j)
                S[ty*4+i][st*64 + tx*4 + j] = acc[i][j];
    }
    __syncthreads();

    // ---- softmax: 4 threads per row ----
    {
        int row = tid >> 2, q = tid & 3;
        int c0 = q*128;
        float mx = -1e30f;
        for (int c = c0; c < c0+128; ++c) mx = fmaxf(mx, S[row][c]);
        mx = fmaxf(mx, __shfl_xor_sync(0xffffffffu, mx, 1));
        mx = fmaxf(mx, __shfl_xor_sync(0xffffffffu, mx, 2));
        float sum = 0.0f;
        for (int c = c0; c < c0+128; ++c) {
            float e = __expf(S[row][c] - mx);
            S[row][c] = e; sum += e;
        }
        sum += __shfl_xor_sync(0xffffffffu, sum, 1);
        sum += __shfl_xor_sync(0xffffffffu, sum, 2);
        float inv = 1.0f / sum;
        for (int c = c0; c < c0+128; ++c) S[row][c] *= inv;
    }
    __syncthreads();

    // ---- write probs (coalesced float4 copy of the whole 64x512 block) ----
    {
        size_t pbase = (((size_t)b*H_ + h)*T_ + t0)*512;
        #pragma unroll
        for (int r = 0; r < 32; ++r) {
            int f4 = tid + r*256;
            *(float4*)(probs + pbase + (size_t)f4*4) = *(float4*)(sm + f4*4);
        }
    }

    // ---- O = P @ V ----
    float acc[4][4] = {};
    for (int st = 0; st < 8; ++st) {
        __syncthreads();
        #pragma unroll
        for (int r = 0; r < 4; ++r) {
            int f4 = tid + r*256;
            int row = f4 >> 4, col = (f4 & 15) * 4;
            *(float4*)&KV[row][col] =
                *(const float4*)&g_v[kvbase + (size_t)(st*64+row)*64 + col];  // natural: KV[s][d]
        }
        __syncthreads();
        #pragma unroll 8
        for (int s = 0; s < 64; ++s) {
            float4 b4 = *(float4*)&KV[s][tx*4];
            float bb[4] = {b4.x, b4.y, b4.z, b4.w};
            float a[4];
            #pragma unroll
            for (int i = 0; i < 4; ++i) a[i] = S[ty*4+i][st*64 + s];
            #pragma unroll
            for (int i = 0; i < 4; ++i)
                #pragma unroll
                for (int j = 0; j < 4; ++j)
                    acc[i][j] = fmaf(a[i], bb[j], acc[i][j]);
        }
    }
    // store O into [B*T, H*D], head-major columns
    {
        size_t obase = ((size_t)b*T_ + t0)*C_ + (size_t)h*64;
        #pragma unroll
        for (int i = 0; i < 4; ++i) {
            float4 v = {acc[i][0], acc[i][1], acc[i][2], acc[i][3]};
            *(float4*)&g_o[obase + (size_t)(ty*4+i)*C_ + tx*4] = v;
        }
    }
}

// --------------------------------- launcher ---------------------------------
extern "C" void kernel_launch(void* const* d_in, const int* in_sizes, int n_in,
                              void* d_out, int out_size)
{
    const float* x     = (const float*)d_in[0];
    const float* Wqkv  = (const float*)d_in[1];
    const float* bqkv  = (const float*)d_in[2];
    const float* Wph   = (const float*)d_in[3];
    const float* bph   = (const float*)d_in[4];
    const float* Wproj = (const float*)d_in[5];
    const float* bproj = (const float*)d_in[6];
    float* out = (float*)d_out;
    float* sa_out = out;                                  // [32,512,768]
    float* probs  = out + (size_t)BT_*C_;                 // [32,12,512,512]

    float* g_wqkvT_p, *g_wcomb_p, *g_bcomb_p, *g_o_p;
    cudaGetSymbolAddress((void**)&g_wqkvT_p, g_wqkvT);
    cudaGetSymbolAddress((void**)&g_wcomb_p, g_wcomb);
    cudaGetSymbolAddress((void**)&g_bcomb_p, g_bcomb);
    cudaGetSymbolAddress((void**)&g_o_p,     g_o);

    // 1. transpose Wqkv -> [C, 2304]
    k_transpose<<<(C_*NQKV_ + 255)/256, 256>>>(Wqkv);
    // 2. combined bias
    k_bcomb<<<3, 256>>>(bph, Wproj, bproj);
    // 3. Wcomb: 12 x [64,768] @ [768,768]
    sgemm_k<64,64,16,4,4,0><<<dim3(1,12,12), 256>>>(
        Wph, Wproj, g_wcomb_p, nullptr,
        64, C_, C_, (long long)64*C_, (long long)C_*C_, (long long)64*C_);
    // 4. QKV GEMM [16384,2304,768] with scatter epilogue
    sgemm_k<128,64,16,8,4,1><<<dim3(BT_/128, NQKV_/64, 1), 256>>>(
        x, g_wqkvT_p, nullptr, bqkv,
        BT_, NQKV_, C_, 0, 0, 0);
    // 5. fused attention
    {
        static int smem_set = 0;
        int smem = (64*512 + 2*64*68) * 4;   // 165,888 B
        if (!smem_set) {
            cudaFuncSetAttribute(attn_k, cudaFuncAttributeMaxDynamicSharedMemorySize, smem);
            smem_set = 1;
        }
        attn_k<<<dim3(T_/64, H_, B_), 256, smem>>>(probs);
    }
    // 6. output GEMM [16384,768,768] + bcomb
    sgemm_k<128,64,16,8,4,0><<<dim3(BT_/128, C_/64, 1), 256>>>(
        g_o_p, g_wcomb_p, sa_out, g_bcomb_p,
        BT_, C_, C_, 0, 0, 0);
}

// round 4
// speedup vs baseline: 1.2835x; 1.2835x over previous
#include <cuda_runtime.h>
#include <cuda_bf16.h>
#include <stdint.h>
#include <math.h>

#define H_   12
#define T_   512
#define D_   64
#define C_   768
#define B_   32
#define NQKV_ 2304
#define BT_  16384
#define QSCALE 0.125f

// ------------- device-global scratch (no runtime alloc allowed) -------------
__device__ __align__(16) __nv_bfloat16 g_xhi[(size_t)BT_*C_];
__device__ __align__(16) __nv_bfloat16 g_xlo[(size_t)BT_*C_];
__device__ __align__(16) __nv_bfloat16 g_wqhi[(size_t)NQKV_*C_];
__device__ __align__(16) __nv_bfloat16 g_wqlo[(size_t)NQKV_*C_];
__device__ __align__(16) float g_q[(size_t)B_*H_*T_*D_];
__device__ __align__(16) float g_k[(size_t)B_*H_*T_*D_];
__device__ __align__(16) float g_v[(size_t)B_*H_*T_*D_];
__device__ __align__(16) __nv_bfloat16 g_ohi[(size_t)BT_*C_];
__device__ __align__(16) __nv_bfloat16 g_olo[(size_t)BT_*C_];
__device__ __align__(16) float g_wcomb[C_*C_];
__device__ __align__(16) __nv_bfloat16 g_wchi[C_*C_];
__device__ __align__(16) __nv_bfloat16 g_wclo[C_*C_];
__device__ __align__(16) float g_bcomb[C_];

// ------------------------------ helpers -------------------------------------
__device__ __forceinline__ uint32_t smem_u32(const void* p) {
    uint32_t a;
    asm("{ .reg .u64 t; cvta.to.shared.u64 t, %1; cvt.u32.u64 %0, t; }"
        : "=r"(a) : "l"(p));
    return a;
}

__device__ __forceinline__ void mma_bf16(float* c, const uint32_t* a,
                                         uint32_t b0, uint32_t b1) {
    asm volatile(
        "mma.sync.aligned.m16n8k16.row.col.f32.bf16.bf16.f32 "
        "{%0,%1,%2,%3}, {%4,%5,%6,%7}, {%8,%9}, {%0,%1,%2,%3};"
        : "+f"(c[0]), "+f"(c[1]), "+f"(c[2]), "+f"(c[3])
        : "r"(a[0]), "r"(a[1]), "r"(a[2]), "r"(a[3]), "r"(b0), "r"(b1));
}

__device__ __forceinline__ void split_bf16(float v, __nv_bfloat16& h, __nv_bfloat16& l) {
    h = __float2bfloat16(v);
    l = __float2bfloat16(v - __bfloat162float(h));
}

// ------------------------------ prep kernels --------------------------------
__global__ void __launch_bounds__(256) k_prep_x(const float* __restrict__ x) {
    size_t i = ((size_t)blockIdx.x * 256 + threadIdx.x) * 4;
    float4 v = *(const float4*)(x + i);
    __nv_bfloat16 h0,h1,h2,h3,l0,l1,l2,l3;
    split_bf16(v.x,h0,l0); split_bf16(v.y,h1,l1);
    split_bf16(v.z,h2,l2); split_bf16(v.w,h3,l3);
    __nv_bfloat162 p;
    p.x=h0; p.y=h1; *(__nv_bfloat162*)(g_xhi+i)   = p;
    p.x=h2; p.y=h3; *(__nv_bfloat162*)(g_xhi+i+2) = p;
    p.x=l0; p.y=l1; *(__nv_bfloat162*)(g_xlo+i)   = p;
    p.x=l2; p.y=l3; *(__nv_bfloat162*)(g_xlo+i+2) = p;
}

__global__ void __launch_bounds__(256) k_prep_wqkv(const float* __restrict__ W) {
    int idx = blockIdx.x * 256 + threadIdx.x;       // n*768 + k
    if (idx >= NQKV_ * C_) return;
    int n = idx / C_, k = idx % C_;
    int h = n / 192, j = n % 192;
    float v = W[((size_t)h * C_ + k) * 192 + j];
    __nv_bfloat16 hi, lo; split_bf16(v, hi, lo);
    g_wqhi[idx] = hi; g_wqlo[idx] = lo;
}

__global__ void __launch_bounds__(256) k_prep_wcombT() {
    int idx = blockIdx.x * 256 + threadIdx.x;       // n*768 + k
    if (idx >= C_ * C_) return;
    int n = idx / C_, k = idx % C_;
    float v = g_wcomb[(size_t)k * C_ + n];
    __nv_bfloat16 hi, lo; split_bf16(v, hi, lo);
    g_wchi[idx] = hi; g_wclo[idx] = lo;
}

__global__ void __launch_bounds__(256) k_bcomb(const float* __restrict__ bph,
                                               const float* __restrict__ Wproj,
                                               const float* __restrict__ bproj) {
    int c = blockIdx.x * 256 + threadIdx.x;
    if (c >= C_) return;
    float acc = bproj[c];
    for (int r = 0; r < H_*C_; ++r)
        acc = fmaf(bph[r], Wproj[(size_t)r*C_ + c], acc);
    g_bcomb[c] = acc;
}

// ----------------- small fp32 SGEMM (Wcomb precompute only) -----------------
__global__ void __launch_bounds__(256) sgemm64(
    const float* __restrict__ A, const float* __restrict__ Bm,
    float* __restrict__ Cm, int M, int N, int K,
    long long sA, long long sB, long long sC)
{
    __shared__ float As[16][68];
    __shared__ float Bs[16][68];
    const float* Ab = A  + (size_t)blockIdx.z * sA;
    const float* Bb = Bm + (size_t)blockIdx.z * sB;
    float*       Cb = Cm + (size_t)blockIdx.z * sC;
    const int tid = threadIdx.x;
    const int tx = tid % 16, ty = tid / 16;
    const int m0 = blockIdx.x * 64, n0 = blockIdx.y * 64;
    float acc[4][4] = {};
    for (int kt = 0; kt < K; kt += 16) {
        {
            int m = tid / 4, kq = (tid % 4) * 4;
            float4 v = *(const float4*)(Ab + (size_t)(m0+m)*K + kt + kq);
            As[kq+0][m] = v.x; As[kq+1][m] = v.y; As[kq+2][m] = v.z; As[kq+3][m] = v.w;
        }
        {
            int kk = tid / 16, nn = (tid % 16) * 4;
            *(float4*)&Bs[kk][nn] = *(const float4*)(Bb + (size_t)(kt+kk)*N + n0 + nn);
        }
        __syncthreads();
        #pragma unroll
        for (int k = 0; k < 16; ++k) {
            float a[4], b[4];
            #pragma unroll
            for (int i = 0; i < 4; ++i) a[i] = As[k][ty*4+i];
            *(float4*)b = *(const float4*)&Bs[k][tx*4];
            #pragma unroll
            for (int i = 0; i < 4; ++i)
                #pragma unroll
                for (int j = 0; j < 4; ++j)
                    acc[i][j] = fmaf(a[i], b[j], acc[i][j]);
        }
        __syncthreads();
    }
    #pragma unroll
    for (int i = 0; i < 4; ++i) {
        int m = m0 + ty*4 + i;
        #pragma unroll
        for (int j = 0; j < 4; ++j)
            Cb[(size_t)m*N + n0 + tx*4 + j] = acc[i][j];
    }
}

// ------------------- HMMA bf16-split GEMM (mma.sync path) -------------------
// C[M, N] = A[M,768] @ W[768,N]; A,B bf16 hi/lo pairs, B stored [n][k].
// CTA tile 128x128, BK=32, double-buffered cp.async.
// smem row stride 80B (40 halves): conflict-free fragment LDS.
// EPI=0: Cout + bias (N=768). EPI=1: q/k/v scatter (N=2304).
#define ROWB 80
#define TILEB (128*ROWB)          // 10240
#define STAGEB (4*TILEB)          // 40960
#define HM_SMEM (2*STAGEB)        // 81920

template<int EPI>
__global__ void __launch_bounds__(256) hmma_gemm(
    const __nv_bfloat16* __restrict__ Ahi, const __nv_bfloat16* __restrict__ Alo,
    const __nv_bfloat16* __restrict__ Bhi, const __nv_bfloat16* __restrict__ Blo,
    float* __restrict__ Cout, const float* __restrict__ bias, int N)
{
    extern __shared__ char smem[];
    const uint32_t sbase = smem_u32(smem);
    const int tid = threadIdx.x;
    const int wid = tid >> 5, ln = tid & 31;
    const int n0 = blockIdx.x * 128, m0 = blockIdx.y * 128;
    const int wm = wid & 3, wn = wid >> 2;      // 4 x 2 warp grid
    const int mrow = wm * 32, ncol = wn * 64;

    const __nv_bfloat16* gsrc[4] = {Ahi, Alo, Bhi, Blo};
    const int rb[4] = {m0, m0, n0, n0};

    auto load_chunk = [&](int kc, int stage) {
        uint32_t sb = sbase + stage * STAGEB;
        #pragma unroll
        for (int f = 0; f < 8; ++f) {
            const int tile = f >> 1;
            int e = (f & 1) * 256 + tid;        // 0..511
            int r = e >> 2, g = e & 3;
            const __nv_bfloat16* gp =
                gsrc[tile] + (size_t)(rb[tile] + r) * C_ + kc * 32 + g * 8;
            uint32_t sa = sb + tile * TILEB + r * ROWB + g * 16;
            asm volatile("cp.async.cg.shared.global [%0], [%1], 16;"
                         :: "r"(sa), "l"(gp));
        }
        asm volatile("cp.async.commit_group;");
    };

    float acc[2][8][4] = {};

    load_chunk(0, 0);
    const int NCH = C_ / 32;                    // 24
    for (int c = 0; c < NCH; ++c) {
        int s = c & 1;
        asm volatile("cp.async.wait_group 0;");
        __syncthreads();                        // chunk c visible; stage s^1 free
        if (c + 1 < NCH) load_chunk(c + 1, s ^ 1);

        uint32_t sA_hi = sbase + s * STAGEB;
        uint32_t sA_lo = sA_hi + TILEB;
        uint32_t sB_hi = sA_hi + 2 * TILEB;
        uint32_t sB_lo = sA_hi + 3 * TILEB;

        #pragma unroll
        for (int ks = 0; ks < 2; ++ks) {
            uint32_t ahi[2][4], alo[2][4];
            int colB = (ks * 16 + (ln & 3) * 2) * 2;     // byte offset in row
            #pragma unroll
            for (int mt = 0; mt < 2; ++mt) {
                uint32_t off = (uint32_t)((mrow + mt*16 + (ln >> 2)) * ROWB + colB);
                asm volatile("ld.shared.b32 %0, [%1];" : "=r"(ahi[mt][0]) : "r"(sA_hi + off));
                asm volatile("ld.shared.b32 %0, [%1];" : "=r"(ahi[mt][1]) : "r"(sA_hi + off + 8*ROWB));
                asm volatile("ld.shared.b32 %0, [%1];" : "=r"(ahi[mt][2]) : "r"(sA_hi + off + 16));
                asm volatile("ld.shared.b32 %0, [%1];" : "=r"(ahi[mt][3]) : "r"(sA_hi + off + 8*ROWB + 16));
                asm volatile("ld.shared.b32 %0, [%1];" : "=r"(alo[mt][0]) : "r"(sA_lo + off));
                asm volatile("ld.shared.b32 %0, [%1];" : "=r"(alo[mt][1]) : "r"(sA_lo + off + 8*ROWB));
                asm volatile("ld.shared.b32 %0, [%1];" : "=r"(alo[mt][2]) : "r"(sA_lo + off + 16));
                asm volatile("ld.shared.b32 %0, [%1];" : "=r"(alo[mt][3]) : "r"(sA_lo + off + 8*ROWB + 16));
            }
            #pragma unroll
            for (int nt = 0; nt < 8; ++nt) {
                uint32_t boff = (uint32_t)((ncol + nt*8 + (ln >> 2)) * ROWB + colB);
                uint32_t bh0, bh1, bl0, bl1;
                asm volatile("ld.shared.b32 %0, [%1];" : "=r"(bh0) : "r"(sB_hi + boff));
                asm volatile("ld.shared.b32 %0, [%1];" : "=r"(bh1) : "r"(sB_hi + boff + 16));
                asm volatile("ld.shared.b32 %0, [%1];" : "=r"(bl0) : "r"(sB_lo + boff));
                asm volatile("ld.shared.b32 %0, [%1];" : "=r"(bl1) : "r"(sB_lo + boff + 16));
                #pragma unroll
                for (int mt = 0; mt < 2; ++mt) {
                    mma_bf16(acc[mt][nt], ahi[mt], bh0, bh1);
                    mma_bf16(acc[mt][nt], ahi[mt], bl0, bl1);
                    mma_bf16(acc[mt][nt], alo[mt], bh0, bh1);
                }
            }
        }
        __syncthreads();                        // compute(s) done before it's reloaded
    }

    // ------------------------------- epilogue --------------------------------
    #pragma unroll
    for (int mt = 0; mt < 2; ++mt) {
        int m = m0 + mrow + mt*16 + (ln >> 2);
        #pragma unroll
        for (int nt = 0; nt < 8; ++nt) {
            int n = n0 + ncol + nt*8 + (ln & 3) * 2;
            float b0 = bias[n], b1 = bias[n+1];
            float* ac = acc[mt][nt];
            if (EPI == 0) {
                float2 v0 = {ac[0] + b0, ac[1] + b1};
                float2 v1 = {ac[2] + b0, ac[3] + b1};
                *(float2*)(Cout + (size_t)m * C_ + n) = v0;
                *(float2*)(Cout + (size_t)(m+8) * C_ + n) = v1;
            } else {
                int h = n / 192, r = n % 192;
                int blk = r >> 6, roff = r & 63;
                float sc = (blk == 0) ? QSCALE : 1.0f;
                float* dst = (blk == 0) ? g_q : ((blk == 1) ? g_k : g_v);
                int b1_ = m >> 9, t1 = m & 511;
                int m2 = m + 8;
                int b2_ = m2 >> 9, t2 = m2 & 511;
                size_t o1 = (((size_t)b1_ * H_ + h) * T_ + t1) * 64 + roff;
                size_t o2 = (((size_t)b2_ * H_ + h) * T_ + t2) * 64 + roff;
                float2 v0 = {(ac[0] + b0) * sc, (ac[1] + b1) * sc};
                float2 v1 = {(ac[2] + b0) * sc, (ac[3] + b1) * sc};
                *(float2*)(dst + o1) = v0;
                *(float2*)(dst + o2) = v1;
            }
        }
    }
}

// ----------------------------- fused attention ------------------------------
// One CTA: (b, h, 64-row q tile). S[64][512] in smem; softmax; probs out; PV.
__global__ void __launch_bounds__(256) attn_k(float* __restrict__ probs)
{
    extern __shared__ float sm[];
    float (*S)[512] = (float(*)[512])sm;                       // 64*512
    float (*Qs)[68] = (float(*)[68])(sm + 64*512);             // 64*68
    float (*KV)[68] = (float(*)[68])(sm + 64*512 + 64*68);     // 64*68

    const int tid = threadIdx.x;
    const int t0 = blockIdx.x * 64;
    const int h = blockIdx.y, b = blockIdx.z;
    const size_t qbase = (((size_t)b*H_ + h)*T_ + t0)*64;
    const size_t kvbase = (((size_t)b*H_ + h)*T_)*64;
    const int tx = tid % 16, ty = tid / 16;

    #pragma unroll
    for (int r = 0; r < 4; ++r) {
        int f4 = tid + r*256;
        int row = f4 >> 4, col = (f4 & 15) * 4;
        *(float4*)&Qs[row][col] = *(const float4*)&g_q[qbase + (size_t)row*64 + col];
    }

    // ---- S = Q @ K^T ----
    for (int st = 0; st < 8; ++st) {
        __syncthreads();
        #pragma unroll
        for (int r = 0; r < 4; ++r) {
            int f4 = tid + r*256;
            int row = f4 >> 4, col = (f4 & 15) * 4;
            float4 v = *(const float4*)&g_k[kvbase + (size_t)(st*64+row)*64 + col];
            KV[col+0][row] = v.x; KV[col+1][row] = v.y;
            KV[col+2][row] = v.z; KV[col+3][row] = v.w;
        }
        __syncthreads();
        float acc[4][4] = {};
        #pragma unroll 8
        for (int d = 0; d < 64; ++d) {
            float4 b4 = *(float4*)&KV[d][tx*4];
            float bb[4] = {b4.x, b4.y, b4.z, b4.w};
            float a[4];
            #pragma unroll
            for (int i = 0; i < 4; ++i) a[i] = Qs[ty*4+i][d];
            #pragma unroll
            for (int i = 0; i < 4; ++i)
                #pragma unroll
                for (int j = 0; j < 4; ++j)
                    acc[i][j] = fmaf(a[i], bb[j], acc[i][j]);
        }
        #pragma unroll
        for (int i = 0; i < 4; ++i)
            #pragma unroll
            for (int j = 0; j < 4; ++j)
                S[ty*4+i][st*64 + tx*4 + j] = acc[i][j];
    }
    __syncthreads();

    // ---- softmax: 4 threads per row ----
    {
        int row = tid >> 2, q = tid & 3;
        int c0 = q*128;
        float mx = -1e30f;
        for (int c = c0; c < c0+128; ++c) mx = fmaxf(mx, S[row][c]);
        mx = fmaxf(mx, __shfl_xor_sync(0xffffffffu, mx, 1));
        mx = fmaxf(mx, __shfl_xor_sync(0xffffffffu, mx, 2));
        float sum = 0.0f;
        for (int c = c0; c < c0+128; ++c) {
            float e = __expf(S[row][c] - mx);
            S[row][c] = e; sum += e;
        }
        sum += __shfl_xor_sync(0xffffffffu, sum, 1);
        sum += __shfl_xor_sync(0xffffffffu, sum, 2);
        float inv = 1.0f / sum;
        for (int c = c0; c < c0+128; ++c) S[row][c] *= inv;
    }
    __syncthreads();

    // ---- write probs ----
    {
        size_t pbase = (((size_t)b*H_ + h)*T_ + t0)*512;
        #pragma unroll
        for (int r = 0; r < 32; ++r) {
            int f4 = tid + r*256;
            *(float4*)(probs + pbase + (size_t)f4*4) = *(float4*)(sm + f4*4);
        }
    }

    // ---- O = P @ V ----
    float acc[4][4] = {};
    for (int st = 0; st < 8; ++st) {
        __syncthreads();
        #pragma unroll
        for (int r = 0; r < 4; ++r) {
            int f4 = tid + r*256;
            int row = f4 >> 4, col = (f4 & 15) * 4;
            *(float4*)&KV[row][col] =
                *(const float4*)&g_v[kvbase + (size_t)(st*64+row)*64 + col];
        }
        __syncthreads();
        #pragma unroll 8
        for (int s = 0; s < 64; ++s) {
            float4 b4 = *(float4*)&KV[s][tx*4];
            float bb[4] = {b4.x, b4.y, b4.z, b4.w};
            float a[4];
            #pragma unroll
            for (int i = 0; i < 4; ++i) a[i] = S[ty*4+i][st*64 + s];
            #pragma unroll
            for (int i = 0; i < 4; ++i)
                #pragma unroll
                for (int j = 0; j < 4; ++j)
                    acc[i][j] = fmaf(a[i], bb[j], acc[i][j]);
        }
    }
    // store O as bf16 hi/lo into [B*T, H*D], head-major columns
    {
        size_t obase = ((size_t)b*T_ + t0)*C_ + (size_t)h*64;
        #pragma unroll
        for (int i = 0; i < 4; ++i) {
            size_t off = obase + (size_t)(ty*4+i)*C_ + tx*4;
            __nv_bfloat16 h0,h1,h2,h3,l0,l1,l2,l3;
            split_bf16(acc[i][0],h0,l0); split_bf16(acc[i][1],h1,l1);
            split_bf16(acc[i][2],h2,l2); split_bf16(acc[i][3],h3,l3);
            __nv_bfloat162 p;
            p.x=h0; p.y=h1; *(__nv_bfloat162*)(g_ohi+off)   = p;
            p.x=h2; p.y=h3; *(__nv_bfloat162*)(g_ohi+off+2) = p;
            p.x=l0; p.y=l1; *(__nv_bfloat162*)(g_olo+off)   = p;
            p.x=l2; p.y=l3; *(__nv_bfloat162*)(g_olo+off+2) = p;
        }
    }
}

// --------------------------------- launcher ---------------------------------
extern "C" void kernel_launch(void* const* d_in, const int* in_sizes, int n_in,
                              void* d_out, int out_size)
{
    const float* x     = (const float*)d_in[0];
    const float* Wqkv  = (const float*)d_in[1];
    const float* bqkv  = (const float*)d_in[2];
    const float* Wph   = (const float*)d_in[3];
    const float* bph   = (const float*)d_in[4];
    const float* Wproj = (const float*)d_in[5];
    const float* bproj = (const float*)d_in[6];
    float* out = (float*)d_out;
    float* sa_out = out;
    float* probs  = out + (size_t)BT_*C_;

    __nv_bfloat16 *xhi_p, *xlo_p, *wqhi_p, *wqlo_p, *ohi_p, *olo_p, *wchi_p, *wclo_p;
    float *wcomb_p, *bcomb_p;
    cudaGetSymbolAddress((void**)&xhi_p,  g_xhi);
    cudaGetSymbolAddress((void**)&xlo_p,  g_xlo);
    cudaGetSymbolAddress((void**)&wqhi_p, g_wqhi);
    cudaGetSymbolAddress((void**)&wqlo_p, g_wqlo);
    cudaGetSymbolAddress((void**)&ohi_p,  g_ohi);
    cudaGetSymbolAddress((void**)&olo_p,  g_olo);
    cudaGetSymbolAddress((void**)&wchi_p, g_wchi);
    cudaGetSymbolAddress((void**)&wclo_p, g_wclo);
    cudaGetSymbolAddress((void**)&wcomb_p, g_wcomb);
    cudaGetSymbolAddress((void**)&bcomb_p, g_bcomb);

    static int attrs_set = 0;
    if (!attrs_set) {
        cudaFuncSetAttribute(hmma_gemm<0>, cudaFuncAttributeMaxDynamicSharedMemorySize, HM_SMEM);
        cudaFuncSetAttribute(hmma_gemm<1>, cudaFuncAttributeMaxDynamicSharedMemorySize, HM_SMEM);
        cudaFuncSetAttribute(attn_k, cudaFuncAttributeMaxDynamicSharedMemorySize,
                             (64*512 + 2*64*68) * 4);
        attrs_set = 1;
    }

    // prep
    k_prep_x<<<BT_*C_/1024, 256>>>(x);
    k_prep_wqkv<<<(NQKV_*C_ + 255)/256, 256>>>(Wqkv);
    k_bcomb<<<3, 256>>>(bph, Wproj, bproj);
    sgemm64<<<dim3(1,12,12), 256>>>(Wph, Wproj, wcomb_p,
        64, C_, C_, (long long)64*C_, (long long)C_*C_, (long long)64*C_);
    k_prep_wcombT<<<(C_*C_ + 255)/256, 256>>>();

    // QKV GEMM: [16384,2304,768] -> q/k/v scatter
    hmma_gemm<1><<<dim3(NQKV_/128, BT_/128), 256, HM_SMEM>>>(
        xhi_p, xlo_p, wqhi_p, wqlo_p, nullptr, bqkv, NQKV_);

    // fused attention -> probs + O(bf16 hi/lo)
    attn_k<<<dim3(T_/64, H_, B_), 256, (64*512 + 2*64*68)*4>>>(probs);

    // output GEMM: [16384,768,768] + bcomb -> sa_out
    hmma_gemm<0><<<dim3(C_/128, BT_/128), 256, HM_SMEM>>>(
        ohi_p, olo_p, wchi_p, wclo_p, sa_out, bcomb_p, C_);
}

// round 5
// speedup vs baseline: 2.8942x; 2.2549x over previous
#include <cuda_runtime.h>
#include <cuda_bf16.h>
#include <stdint.h>
#include <math.h>

#define H_   12
#define T_   512
#define D_   64
#define C_   768
#define B_   32
#define NQKV_ 2304
#define BT_  16384
#define BHTD_ ((size_t)B_*H_*T_*D_)
#define QSCALE 0.125f

// ------------- device-global scratch (no runtime alloc allowed) -------------
__device__ __align__(16) __nv_bfloat16 g_xhi[(size_t)BT_*C_];
__device__ __align__(16) __nv_bfloat16 g_xlo[(size_t)BT_*C_];
__device__ __align__(16) __nv_bfloat16 g_wqhi[(size_t)NQKV_*C_];
__device__ __align__(16) __nv_bfloat16 g_wqlo[(size_t)NQKV_*C_];
__device__ __align__(16) __nv_bfloat16 g_qhi[BHTD_];
__device__ __align__(16) __nv_bfloat16 g_qlo[BHTD_];
__device__ __align__(16) __nv_bfloat16 g_khi[BHTD_];
__device__ __align__(16) __nv_bfloat16 g_klo[BHTD_];
__device__ __align__(16) __nv_bfloat16 g_vhi[BHTD_];
__device__ __align__(16) __nv_bfloat16 g_vlo[BHTD_];
__device__ __align__(16) __nv_bfloat16 g_vthi[BHTD_];   // [b,h,d,s]
__device__ __align__(16) __nv_bfloat16 g_vtlo[BHTD_];
__device__ __align__(16) __nv_bfloat16 g_ohi[(size_t)BT_*C_];
__device__ __align__(16) __nv_bfloat16 g_olo[(size_t)BT_*C_];
__device__ __align__(16) float g_wcomb[C_*C_];
__device__ __align__(16) __nv_bfloat16 g_wchi[C_*C_];
__device__ __align__(16) __nv_bfloat16 g_wclo[C_*C_];
__device__ __align__(16) float g_bcomb[C_];

// ------------------------------ helpers -------------------------------------
__device__ __forceinline__ uint32_t smem_u32(const void* p) {
    uint32_t a;
    asm("{ .reg .u64 t; cvta.to.shared.u64 t, %1; cvt.u32.u64 %0, t; }"
        : "=r"(a) : "l"(p));
    return a;
}
__device__ __forceinline__ void mma_bf16(float* c, const uint32_t* a,
                                         uint32_t b0, uint32_t b1) {
    asm volatile(
        "mma.sync.aligned.m16n8k16.row.col.f32.bf16.bf16.f32 "
        "{%0,%1,%2,%3}, {%4,%5,%6,%7}, {%8,%9}, {%0,%1,%2,%3};"
        : "+f"(c[0]), "+f"(c[1]), "+f"(c[2]), "+f"(c[3])
        : "r"(a[0]), "r"(a[1]), "r"(a[2]), "r"(a[3]), "r"(b0), "r"(b1));
}
__device__ __forceinline__ uint32_t lds32(uint32_t a) {
    uint32_t v;
    asm volatile("ld.shared.b32 %0, [%1];" : "=r"(v) : "r"(a));
    return v;
}
__device__ __forceinline__ void split_bf16(float v, __nv_bfloat16& h, __nv_bfloat16& l) {
    h = __float2bfloat16(v);
    l = __float2bfloat16(v - __bfloat162float(h));
}
__device__ __forceinline__ uint32_t pack2(float a, float b) {   // a -> low
    __nv_bfloat162 t = __floats2bfloat162_rn(a, b);
    return *(uint32_t*)&t;
}
__device__ __forceinline__ float resid(float v) {
    return v - __bfloat162float(__float2bfloat16(v));
}

// ------------------------------ prep kernels --------------------------------
__global__ void __launch_bounds__(256) k_prep_x(const float* __restrict__ x) {
    size_t i = ((size_t)blockIdx.x * 256 + threadIdx.x) * 4;
    float4 v = *(const float4*)(x + i);
    __nv_bfloat16 h0,h1,h2,h3,l0,l1,l2,l3;
    split_bf16(v.x,h0,l0); split_bf16(v.y,h1,l1);
    split_bf16(v.z,h2,l2); split_bf16(v.w,h3,l3);
    __nv_bfloat162 p;
    p.x=h0; p.y=h1; *(__nv_bfloat162*)(g_xhi+i)   = p;
    p.x=h2; p.y=h3; *(__nv_bfloat162*)(g_xhi+i+2) = p;
    p.x=l0; p.y=l1; *(__nv_bfloat162*)(g_xlo+i)   = p;
    p.x=l2; p.y=l3; *(__nv_bfloat162*)(g_xlo+i+2) = p;
}

__global__ void __launch_bounds__(256) k_prep_wqkv(const float* __restrict__ W) {
    int idx = blockIdx.x * 256 + threadIdx.x;       // n*768 + k
    if (idx >= NQKV_ * C_) return;
    int n = idx / C_, k = idx % C_;
    int h = n / 192, j = n % 192;
    float v = W[((size_t)h * C_ + k) * 192 + j];
    __nv_bfloat16 hi, lo; split_bf16(v, hi, lo);
    g_wqhi[idx] = hi; g_wqlo[idx] = lo;
}

__global__ void __launch_bounds__(256) k_prep_wcombT() {
    int idx = blockIdx.x * 256 + threadIdx.x;       // n*768 + k
    if (idx >= C_ * C_) return;
    int n = idx / C_, k = idx % C_;
    float v = g_wcomb[(size_t)k * C_ + n];
    __nv_bfloat16 hi, lo; split_bf16(v, hi, lo);
    g_wchi[idx] = hi; g_wclo[idx] = lo;
}

__global__ void __launch_bounds__(256) k_binit(const float* __restrict__ bproj) {
    int c = blockIdx.x * 256 + threadIdx.x;
    if (c < C_) g_bcomb[c] = bproj[c];
}

__global__ void __launch_bounds__(256) k_bcomb(const float* __restrict__ bph,
                                               const float* __restrict__ Wproj) {
    int r0 = blockIdx.x * 128;
    int t = threadIdx.x;
    float a0 = 0.f, a1 = 0.f, a2 = 0.f;
    for (int rr = 0; rr < 128; ++rr) {
        int r = r0 + rr;
        float bv = bph[r];
        const float* wr = Wproj + (size_t)r * C_;
        a0 = fmaf(bv, wr[t],       a0);
        a1 = fmaf(bv, wr[t + 256], a1);
        a2 = fmaf(bv, wr[t + 512], a2);
    }
    atomicAdd(&g_bcomb[t],       a0);
    atomicAdd(&g_bcomb[t + 256], a1);
    atomicAdd(&g_bcomb[t + 512], a2);
}

// ----------------- small fp32 SGEMM (Wcomb precompute only) -----------------
__global__ void __launch_bounds__(256) sgemm64(
    const float* __restrict__ A, const float* __restrict__ Bm,
    float* __restrict__ Cm, int M, int N, int K,
    long long sA, long long sB, long long sC)
{
    __shared__ float As[16][68];
    __shared__ float Bs[16][68];
    const float* Ab = A  + (size_t)blockIdx.z * sA;
    const float* Bb = Bm + (size_t)blockIdx.z * sB;
    float*       Cb = Cm + (size_t)blockIdx.z * sC;
    const int tid = threadIdx.x;
    const int tx = tid % 16, ty = tid / 16;
    const int m0 = blockIdx.x * 64, n0 = blockIdx.y * 64;
    float acc[4][4] = {};
    for (int kt = 0; kt < K; kt += 16) {
        {
            int m = tid / 4, kq = (tid % 4) * 4;
            float4 v = *(const float4*)(Ab + (size_t)(m0+m)*K + kt + kq);
            As[kq+0][m] = v.x; As[kq+1][m] = v.y; As[kq+2][m] = v.z; As[kq+3][m] = v.w;
        }
        {
            int kk = tid / 16, nn = (tid % 16) * 4;
            *(float4*)&Bs[kk][nn] = *(const float4*)(Bb + (size_t)(kt+kk)*N + n0 + nn);
        }
        __syncthreads();
        #pragma unroll
        for (int k = 0; k < 16; ++k) {
            float a[4], b[4];
            #pragma unroll
            for (int i = 0; i < 4; ++i) a[i] = As[k][ty*4+i];
            *(float4*)b = *(const float4*)&Bs[k][tx*4];
            #pragma unroll
            for (int i = 0; i < 4; ++i)
                #pragma unroll
                for (int j = 0; j < 4; ++j)
                    acc[i][j] = fmaf(a[i], b[j], acc[i][j]);
        }
        __syncthreads();
    }
    #pragma unroll
    for (int i = 0; i < 4; ++i) {
        int m = m0 + ty*4 + i;
        #pragma unroll
        for (int j = 0; j < 4; ++j)
            Cb[(size_t)m*N + n0 + tx*4 + j] = acc[i][j];
    }
}

// ------------------- HMMA bf16-split GEMM -----------------------------------
#define ROWB 80
#define TILEB (128*ROWB)
#define STAGEB (4*TILEB)
#define HM_SMEM (2*STAGEB)

template<int EPI>
__global__ void __launch_bounds__(256) hmma_gemm(
    const __nv_bfloat16* __restrict__ Ahi, const __nv_bfloat16* __restrict__ Alo,
    const __nv_bfloat16* __restrict__ Bhi, const __nv_bfloat16* __restrict__ Blo,
    float* __restrict__ Cout, const float* __restrict__ bias, int N)
{
    extern __shared__ char smem[];
    const uint32_t sbase = smem_u32(smem);
    const int tid = threadIdx.x;
    const int wid = tid >> 5, ln = tid & 31;
    const int n0 = blockIdx.x * 128, m0 = blockIdx.y * 128;
    const int wm = wid & 3, wn = wid >> 2;
    const int mrow = wm * 32, ncol = wn * 64;

    const __nv_bfloat16* gsrc[4] = {Ahi, Alo, Bhi, Blo};
    const int rb[4] = {m0, m0, n0, n0};

    auto load_chunk = [&](int kc, int stage) {
        uint32_t sb = sbase + stage * STAGEB;
        #pragma unroll
        for (int f = 0; f < 8; ++f) {
            const int tile = f >> 1;
            int e = (f & 1) * 256 + tid;
            int r = e >> 2, g = e & 3;
            const __nv_bfloat16* gp =
                gsrc[tile] + (size_t)(rb[tile] + r) * C_ + kc * 32 + g * 8;
            uint32_t sa = sb + tile * TILEB + r * ROWB + g * 16;
            asm volatile("cp.async.cg.shared.global [%0], [%1], 16;"
                         :: "r"(sa), "l"(gp));
        }
        asm volatile("cp.async.commit_group;");
    };

    float acc[2][8][4] = {};

    load_chunk(0, 0);
    const int NCH = C_ / 32;
    for (int c = 0; c < NCH; ++c) {
        int s = c & 1;
        asm volatile("cp.async.wait_group 0;");
        __syncthreads();
        if (c + 1 < NCH) load_chunk(c + 1, s ^ 1);

        uint32_t sA_hi = sbase + s * STAGEB;
        uint32_t sA_lo = sA_hi + TILEB;
        uint32_t sB_hi = sA_hi + 2 * TILEB;
        uint32_t sB_lo = sA_hi + 3 * TILEB;

        #pragma unroll
        for (int ks = 0; ks < 2; ++ks) {
            uint32_t ahi[2][4], alo[2][4];
            int colB = (ks * 16 + (ln & 3) * 2) * 2;
            #pragma unroll
            for (int mt = 0; mt < 2; ++mt) {
                uint32_t off = (uint32_t)((mrow + mt*16 + (ln >> 2)) * ROWB + colB);
                ahi[mt][0] = lds32(sA_hi + off);
                ahi[mt][1] = lds32(sA_hi + off + 8*ROWB);
                ahi[mt][2] = lds32(sA_hi + off + 16);
                ahi[mt][3] = lds32(sA_hi + off + 8*ROWB + 16);
                alo[mt][0] = lds32(sA_lo + off);
                alo[mt][1] = lds32(sA_lo + off + 8*ROWB);
                alo[mt][2] = lds32(sA_lo + off + 16);
                alo[mt][3] = lds32(sA_lo + off + 8*ROWB + 16);
            }
            #pragma unroll
            for (int nt = 0; nt < 8; ++nt) {
                uint32_t boff = (uint32_t)((ncol + nt*8 + (ln >> 2)) * ROWB + colB);
                uint32_t bh0 = lds32(sB_hi + boff);
                uint32_t bh1 = lds32(sB_hi + boff + 16);
                uint32_t bl0 = lds32(sB_lo + boff);
                uint32_t bl1 = lds32(sB_lo + boff + 16);
                #pragma unroll
                for (int mt = 0; mt < 2; ++mt) {
                    mma_bf16(acc[mt][nt], ahi[mt], bh0, bh1);
                    mma_bf16(acc[mt][nt], ahi[mt], bl0, bl1);
                    mma_bf16(acc[mt][nt], alo[mt], bh0, bh1);
                }
            }
        }
        __syncthreads();
    }

    // ------------------------------- epilogue --------------------------------
    #pragma unroll
    for (int mt = 0; mt < 2; ++mt) {
        int m = m0 + mrow + mt*16 + (ln >> 2);
        #pragma unroll
        for (int nt = 0; nt < 8; ++nt) {
            int n = n0 + ncol + nt*8 + (ln & 3) * 2;
            float b0 = bias[n], b1 = bias[n+1];
            float* ac = acc[mt][nt];
            if (EPI == 0) {
                float2 v0 = {ac[0] + b0, ac[1] + b1};
                float2 v1 = {ac[2] + b0, ac[3] + b1};
                *(float2*)(Cout + (size_t)m * C_ + n) = v0;
                *(float2*)(Cout + (size_t)(m+8) * C_ + n) = v1;
            } else {
                int h = n / 192, r = n % 192;
                int blk = r >> 6, roff = r & 63;
                float sc = (blk == 0) ? QSCALE : 1.0f;
                __nv_bfloat16* dhi = (blk == 0) ? g_qhi : ((blk == 1) ? g_khi : g_vhi);
                __nv_bfloat16* dlo = (blk == 0) ? g_qlo : ((blk == 1) ? g_klo : g_vlo);
                #pragma unroll
                for (int rr = 0; rr < 2; ++rr) {
                    int mm = m + rr*8;
                    int b_ = mm >> 9, t_ = mm & 511;
                    size_t o = (((size_t)b_ * H_ + h) * T_ + t_) * 64 + roff;
                    float v0 = (ac[rr*2+0] + b0) * sc;
                    float v1 = (ac[rr*2+1] + b1) * sc;
                    __nv_bfloat16 h0,h1,l0,l1;
                    split_bf16(v0,h0,l0); split_bf16(v1,h1,l1);
                    __nv_bfloat162 ph; ph.x=h0; ph.y=h1;
                    __nv_bfloat162 pl; pl.x=l0; pl.y=l1;
                    *(__nv_bfloat162*)(dhi + o) = ph;
                    *(__nv_bfloat162*)(dlo + o) = pl;
                }
            }
        }
    }
}

// ------------------------ V transpose: [s][d] -> [d][s] ----------------------
__global__ void __launch_bounds__(256) k_vT() {
    __shared__ __nv_bfloat16 thi[64][72];
    __shared__ __nv_bfloat16 tlo[64][72];
    const int s0 = blockIdx.x * 64;
    const int bh = blockIdx.y;
    const int tid = threadIdx.x;
    const int r = tid >> 2, cs = (tid & 3) * 16;
    const size_t sbase = ((size_t)bh * T_ + s0 + r) * 64 + cs;
    #pragma unroll
    for (int j = 0; j < 2; ++j) {
        *(uint4*)&thi[r][cs + j*8] = *(const uint4*)(g_vhi + sbase + j*8);
        *(uint4*)&tlo[r][cs + j*8] = *(const uint4*)(g_vlo + sbase + j*8);
    }
    __syncthreads();
    const int d = tid >> 2, ss = (tid & 3) * 16;
    const size_t dbase = ((size_t)bh * 64 + d) * T_ + s0 + ss;
    #pragma unroll
    for (int j = 0; j < 2; ++j) {
        uint32_t ph[4], pl[4];
        #pragma unroll
        for (int q = 0; q < 4; ++q) {
            int s = ss + j*8 + q*2;
            __nv_bfloat162 a; a.x = thi[s][d]; a.y = thi[s+1][d];
            ph[q] = *(uint32_t*)&a;
            __nv_bfloat162 b2; b2.x = tlo[s][d]; b2.y = tlo[s+1][d];
            pl[q] = *(uint32_t*)&b2;
        }
        *(uint4*)(g_vthi + dbase + j*8) = *(uint4*)ph;
        *(uint4*)(g_vtlo + dbase + j*8) = *(uint4*)pl;
    }
}

// --------------------------- HMMA fused attention ----------------------------
// CTA = (b, h, 64 q rows). 512 thr / 16 warps: wm = wid&3 (16 rows), wq = wid>>2
// (128 keys). S in registers via mma; softmax in regs; probs direct from regs;
// PV re-packs S accum as A-fragments; V from pre-transposed VT.
#define KSTR 144u
#define QSTR 144u
#define VTSTR 1040u
#define SM_K 0u
#define SM_KLO 73728u
#define SM_VT 0u
#define SM_VTLO 66560u
#define SM_Q 147456u
#define SM_QLO 156672u
#define SM_OBUF 147456u
#define OSTRF 72
#define SM_EXM 165888u
#define SM_EXS 166912u
#define ATTN_SMEM 167936

__global__ void __launch_bounds__(512) attn_k(float* __restrict__ probs)
{
    extern __shared__ char smem[];
    const uint32_t sb = smem_u32(smem);
    const int tid = threadIdx.x;
    const int wid = tid >> 5, ln = tid & 31;
    const int wm = wid & 3, wq = wid >> 2;
    const int b = blockIdx.z, h = blockIdx.y, t0 = blockIdx.x * 64;
    const int bh = b * H_ + h;
    const int lr = ln >> 2, lc = ln & 3;

    // ---- load K (full 512) + Q (64 rows), hi/lo, padded rows ----
    {
        const __nv_bfloat16* khi = g_khi + (size_t)bh * T_ * 64;
        const __nv_bfloat16* klo = g_klo + (size_t)bh * T_ * 64;
        #pragma unroll
        for (int i = 0; i < 8; ++i) {
            int idx = tid + i * 512;
            int r = idx >> 3, sg = idx & 7;
            asm volatile("cp.async.cg.shared.global [%0], [%1], 16;"
                :: "r"(sb + SM_K + r*KSTR + sg*16), "l"(khi + (size_t)r*64 + sg*8));
        }
        #pragma unroll
        for (int i = 0; i < 8; ++i) {
            int idx = tid + i * 512;
            int r = idx >> 3, sg = idx & 7;
            asm volatile("cp.async.cg.shared.global [%0], [%1], 16;"
                :: "r"(sb + SM_KLO + r*KSTR + sg*16), "l"(klo + (size_t)r*64 + sg*8));
        }
        const __nv_bfloat16* qhi = g_qhi + ((size_t)bh * T_ + t0) * 64;
        const __nv_bfloat16* qlo = g_qlo + ((size_t)bh * T_ + t0) * 64;
        {
            int r = tid >> 3, sg = tid & 7;
            asm volatile("cp.async.cg.shared.global [%0], [%1], 16;"
                :: "r"(sb + SM_Q + r*QSTR + sg*16), "l"(qhi + (size_t)r*64 + sg*8));
            asm volatile("cp.async.cg.shared.global [%0], [%1], 16;"
                :: "r"(sb + SM_QLO + r*QSTR + sg*16), "l"(qlo + (size_t)r*64 + sg*8));
        }
        asm volatile("cp.async.commit_group;");
        asm volatile("cp.async.wait_group 0;");
    }
    __syncthreads();

    // ---- Q fragments (held in regs for all 4 k-steps) ----
    uint32_t aH[4][4], aL[4][4];
    {
        const int row = wm * 16 + lr;
        #pragma unroll
        for (int ks = 0; ks < 4; ++ks) {
            uint32_t off = row * QSTR + ks * 32 + lc * 4;
            aH[ks][0] = lds32(sb + SM_Q + off);
            aH[ks][1] = lds32(sb + SM_Q + off + 8*QSTR);
            aH[ks][2] = lds32(sb + SM_Q + off + 16);
            aH[ks][3] = lds32(sb + SM_Q + off + 8*QSTR + 16);
            aL[ks][0] = lds32(sb + SM_QLO + off);
            aL[ks][1] = lds32(sb + SM_QLO + off + 8*QSTR);
            aL[ks][2] = lds32(sb + SM_QLO + off + 16);
            aL[ks][3] = lds32(sb + SM_QLO + off + 8*QSTR + 16);
        }
    }

    // ---- S = Q K^T into registers: 16 n-tiles of 8 keys ----
    float acc[16][4];
    #pragma unroll
    for (int nt = 0; nt < 16; ++nt) { acc[nt][0]=acc[nt][1]=acc[nt][2]=acc[nt][3]=0.f; }
    #pragma unroll
    for (int nt = 0; nt < 16; ++nt) {
        uint32_t krow = (uint32_t)(wq * 128 + nt * 8 + lr);
        #pragma unroll
        for (int ks = 0; ks < 4; ++ks) {
            uint32_t boff = krow * KSTR + ks * 32 + lc * 4;
            uint32_t bh0 = lds32(sb + SM_K + boff);
            uint32_t bh1 = lds32(sb + SM_K + boff + 16);
            uint32_t bl0 = lds32(sb + SM_KLO + boff);
            uint32_t bl1 = lds32(sb + SM_KLO + boff + 16);
            mma_bf16(acc[nt], aH[ks], bh0, bh1);
            mma_bf16(acc[nt], aH[ks], bl0, bl1);
            mma_bf16(acc[nt], aL[ks], bh0, bh1);
        }
    }

    // ---- softmax over 512 keys (quad shfl + 4-warp smem exchange) ----
    const int row0 = wm * 16 + lr;      // local row for value pair (d0,d1)
    {
        float mx0 = -1e30f, mx1 = -1e30f;
        #pragma unroll
        for (int nt = 0; nt < 16; ++nt) {
            mx0 = fmaxf(mx0, fmaxf(acc[nt][0], acc[nt][1]));
            mx1 = fmaxf(mx1, fmaxf(acc[nt][2], acc[nt][3]));
        }
        mx0 = fmaxf(mx0, __shfl_xor_sync(0xffffffffu, mx0, 1));
        mx0 = fmaxf(mx0, __shfl_xor_sync(0xffffffffu, mx0, 2));
        mx1 = fmaxf(mx1, __shfl_xor_sync(0xffffffffu, mx1, 1));
        mx1 = fmaxf(mx1, __shfl_xor_sync(0xffffffffu, mx1, 2));
        float* exm = (float*)(smem + SM_EXM);
        if (lc == 0) { exm[wq*64 + row0] = mx0; exm[wq*64 + row0 + 8] = mx1; }
        __syncthreads();
        float m0 = fmaxf(fmaxf(exm[row0],      exm[64+row0]),
                         fmaxf(exm[128+row0],  exm[192+row0]));
        float m1 = fmaxf(fmaxf(exm[row0+8],    exm[64+row0+8]),
                         fmaxf(exm[128+row0+8],exm[192+row0+8]));
        float s0 = 0.f, s1 = 0.f;
        #pragma unroll
        for (int nt = 0; nt < 16; ++nt) {
            acc[nt][0] = __expf(acc[nt][0] - m0); s0 += acc[nt][0];
            acc[nt][1] = __expf(acc[nt][1] - m0); s0 += acc[nt][1];
            acc[nt][2] = __expf(acc[nt][2] - m1); s1 += acc[nt][2];
            acc[nt][3] = __expf(acc[nt][3] - m1); s1 += acc[nt][3];
        }
        s0 += __shfl_xor_sync(0xffffffffu, s0, 1);
        s0 += __shfl_xor_sync(0xffffffffu, s0, 2);
        s1 += __shfl_xor_sync(0xffffffffu, s1, 1);
        s1 += __shfl_xor_sync(0xffffffffu, s1, 2);
        float* exs = (float*)(smem + SM_EXS);
        if (lc == 0) { exs[wq*64 + row0] = s0; exs[wq*64 + row0 + 8] = s1; }
        __syncthreads();
        float inv0 = 1.0f / (exs[row0] + exs[64+row0] + exs[128+row0] + exs[192+row0]);
        float inv1 = 1.0f / (exs[row0+8] + exs[64+row0+8] + exs[128+row0+8] + exs[192+row0+8]);
        #pragma unroll
        for (int nt = 0; nt < 16; ++nt) {
            acc[nt][0] *= inv0; acc[nt][1] *= inv0;
            acc[nt][2] *= inv1; acc[nt][3] *= inv1;
        }
    }

    // ---- write probs straight from registers (32B quad segments) ----
    {
        float* p0 = probs + ((size_t)bh * T_ + t0 + row0) * 512 + wq*128 + lc*2;
        float* p1 = p0 + (size_t)8 * 512;
        #pragma unroll
        for (int nt = 0; nt < 16; ++nt) {
            float2 v0 = {acc[nt][0], acc[nt][1]};
            float2 v1 = {acc[nt][2], acc[nt][3]};
            *(float2*)(p0 + nt*8) = v0;
            *(float2*)(p1 + nt*8) = v1;
        }
    }

    // ---- load VT [d][s] into K region (now free) ----
    __syncthreads();
    {
        const __nv_bfloat16* vthi = g_vthi + (size_t)bh * 64 * T_;
        const __nv_bfloat16* vtlo = g_vtlo + (size_t)bh * 64 * T_;
        #pragma unroll
        for (int i = 0; i < 8; ++i) {
            int idx = tid + i * 512;
            int d = idx >> 6, sg = idx & 63;
            asm volatile("cp.async.cg.shared.global [%0], [%1], 16;"
                :: "r"(sb + SM_VT + d*VTSTR + sg*16), "l"(vthi + (size_t)d*T_ + sg*8));
        }
        #pragma unroll
        for (int i = 0; i < 8; ++i) {
            int idx = tid + i * 512;
            int d = idx >> 6, sg = idx & 63;
            asm volatile("cp.async.cg.shared.global [%0], [%1], 16;"
                :: "r"(sb + SM_VTLO + d*VTSTR + sg*16), "l"(vtlo + (size_t)d*T_ + sg*8));
        }
        asm volatile("cp.async.commit_group;");
        asm volatile("cp.async.wait_group 0;");
    }
    __syncthreads();

    // ---- O_partial = P(warp's 128 keys) @ V ----
    float oacc[8][4];
    #pragma unroll
    for (int dn = 0; dn < 8; ++dn) { oacc[dn][0]=oacc[dn][1]=oacc[dn][2]=oacc[dn][3]=0.f; }
    #pragma unroll
    for (int kk = 0; kk < 8; ++kk) {
        uint32_t phi[4], plo[4];
        phi[0] = pack2(acc[2*kk][0],   acc[2*kk][1]);
        phi[1] = pack2(acc[2*kk][2],   acc[2*kk][3]);
        phi[2] = pack2(acc[2*kk+1][0], acc[2*kk+1][1]);
        phi[3] = pack2(acc[2*kk+1][2], acc[2*kk+1][3]);
        plo[0] = pack2(resid(acc[2*kk][0]),   resid(acc[2*kk][1]));
        plo[1] = pack2(resid(acc[2*kk][2]),   resid(acc[2*kk][3]));
        plo[2] = pack2(resid(acc[2*kk+1][0]), resid(acc[2*kk+1][1]));
        plo[3] = pack2(resid(acc[2*kk+1][2]), resid(acc[2*kk+1][3]));
        uint32_t colV = (uint32_t)((wq*128 + kk*16 + lc*2) * 2);
        #pragma unroll
        for (int dn = 0; dn < 8; ++dn) {
            uint32_t vrow = (uint32_t)(dn*8 + lr);
            uint32_t offH = vrow * VTSTR + colV;
            uint32_t bh0 = lds32(sb + SM_VT + offH);
            uint32_t bh1 = lds32(sb + SM_VT + offH + 16);
            uint32_t bl0 = lds32(sb + SM_VTLO + offH);
            uint32_t bl1 = lds32(sb + SM_VTLO + offH + 16);
            mma_bf16(oacc[dn], phi, bh0, bh1);
            mma_bf16(oacc[dn], phi, bl0, bl1);
            mma_bf16(oacc[dn], plo, bh0, bh1);
        }
    }

    // ---- 4-way cross-warp reduce into O buffer (overlays Q region) ----
    float* obuf = (float*)(smem + SM_OBUF);
    #pragma unroll
    for (int g = 0; g < 4; ++g) {
        if (wq == g) {
            #pragma unroll
            for (int dn = 0; dn < 8; ++dn) {
                int c = dn*8 + lc*2;
                float* b0 = obuf + row0 * OSTRF + c;
                float* b1 = obuf + (row0 + 8) * OSTRF + c;
                if (g == 0) {
                    b0[0] = oacc[dn][0]; b0[1] = oacc[dn][1];
                    b1[0] = oacc[dn][2]; b1[1] = oacc[dn][3];
                } else {
                    b0[0] += oacc[dn][0]; b0[1] += oacc[dn][1];
                    b1[0] += oacc[dn][2]; b1[1] += oacc[dn][3];
                }
            }
        }
        __syncthreads();
    }

    // ---- write O as bf16 hi/lo ----
    {
        int row = tid >> 3, d0 = (tid & 7) * 8;
        const float* src = obuf + row * OSTRF + d0;
        uint32_t ph[4], pl[4];
        #pragma unroll
        for (int q = 0; q < 4; ++q) {
            float v0 = src[q*2], v1 = src[q*2+1];
            __nv_bfloat16 h0,h1,l0,l1;
            split_bf16(v0,h0,l0); split_bf16(v1,h1,l1);
            __nv_bfloat162 a; a.x=h0; a.y=h1; ph[q] = *(uint32_t*)&a;
            __nv_bfloat162 c2; c2.x=l0; c2.y=l1; pl[q] = *(uint32_t*)&c2;
        }
        size_t dst = ((size_t)b * T_ + t0 + row) * C_ + h * 64 + d0;
        *(uint4*)(g_ohi + dst) = *(uint4*)ph;
        *(uint4*)(g_olo + dst) = *(uint4*)pl;
    }
}

// --------------------------------- launcher ---------------------------------
extern "C" void kernel_launch(void* const* d_in, const int* in_sizes, int n_in,
                              void* d_out, int out_size)
{
    const float* x     = (const float*)d_in[0];
    const float* Wqkv  = (const float*)d_in[1];
    const float* bqkv  = (const float*)d_in[2];
    const float* Wph   = (const float*)d_in[3];
    const float* bph   = (const float*)d_in[4];
    const float* Wproj = (const float*)d_in[5];
    const float* bproj = (const float*)d_in[6];
    float* out = (float*)d_out;
    float* sa_out = out;
    float* probs  = out + (size_t)BT_*C_;

    __nv_bfloat16 *xhi_p, *xlo_p, *wqhi_p, *wqlo_p, *ohi_p, *olo_p, *wchi_p, *wclo_p;
    float *wcomb_p, *bcomb_p;
    cudaGetSymbolAddress((void**)&xhi_p,  g_xhi);
    cudaGetSymbolAddress((void**)&xlo_p,  g_xlo);
    cudaGetSymbolAddress((void**)&wqhi_p, g_wqhi);
    cudaGetSymbolAddress((void**)&wqlo_p, g_wqlo);
    cudaGetSymbolAddress((void**)&ohi_p,  g_ohi);
    cudaGetSymbolAddress((void**)&olo_p,  g_olo);
    cudaGetSymbolAddress((void**)&wchi_p, g_wchi);
    cudaGetSymbolAddress((void**)&wclo_p, g_wclo);
    cudaGetSymbolAddress((void**)&wcomb_p, g_wcomb);
    cudaGetSymbolAddress((void**)&bcomb_p, g_bcomb);

    static int attrs_set = 0;
    if (!attrs_set) {
        cudaFuncSetAttribute(hmma_gemm<0>, cudaFuncAttributeMaxDynamicSharedMemorySize, HM_SMEM);
        cudaFuncSetAttribute(hmma_gemm<1>, cudaFuncAttributeMaxDynamicSharedMemorySize, HM_SMEM);
        cudaFuncSetAttribute(attn_k, cudaFuncAttributeMaxDynamicSharedMemorySize, ATTN_SMEM);
        attrs_set = 1;
    }

    // prep
    k_prep_x<<<BT_*C_/1024, 256>>>(x);
    k_prep_wqkv<<<(NQKV_*C_ + 255)/256, 256>>>(Wqkv);
    k_binit<<<3, 256>>>(bproj);
    k_bcomb<<<72, 256>>>(bph, Wproj);
    sgemm64<<<dim3(1,12,12), 256>>>(Wph, Wproj, wcomb_p,
        64, C_, C_, (long long)64*C_, (long long)C_*C_, (long long)64*C_);
    k_prep_wcombT<<<(C_*C_ + 255)/256, 256>>>();

    // QKV GEMM -> q/k/v bf16 hi/lo (q pre-scaled)
    hmma_gemm<1><<<dim3(NQKV_/128, BT_/128), 256, HM_SMEM>>>(
        xhi_p, xlo_p, wqhi_p, wqlo_p, nullptr, bqkv, NQKV_);

    // V transpose -> [b,h,d,s]
    k_vT<<<dim3(T_/64, B_*H_), 256>>>();

    // HMMA fused attention -> probs + O(bf16 hi/lo)
    attn_k<<<dim3(T_/64, H_, B_), 512, ATTN_SMEM>>>(probs);

    // output GEMM + bcomb -> sa_out
    hmma_gemm<0><<<dim3(C_/128, BT_/128), 256, HM_SMEM>>>(
        ohi_p, olo_p, wchi_p, wclo_p, sa_out, bcomb_p, C_);
}

// round 6
// speedup vs baseline: 3.3250x; 1.1488x over previous
#include <cuda_runtime.h>
#include <cuda_bf16.h>
#include <stdint.h>
#include <math.h>

#define H_   12
#define T_   512
#define D_   64
#define C_   768
#define B_   32
#define NQKV_ 2304
#define BT_  16384
#define BHTD_ ((size_t)B_*H_*T_*D_)
#define QSCALE 0.125f

// ------------- device-global scratch (no runtime alloc allowed) -------------
// combined layout: per row, 48 groups of 64B; each group g covers k=16g..16g+15;
// 16B granule lc (0..3) = [hi(2lc),hi(2lc+1),hi(2lc+8),hi(2lc+9) | lo(same)]
__device__ __align__(16) uint8_t g_xc[(size_t)BT_*3072];
__device__ __align__(16) uint8_t g_wqc[(size_t)NQKV_*3072];
__device__ __align__(16) uint8_t g_oc[(size_t)BT_*3072];
__device__ __align__(16) uint8_t g_wcc[(size_t)C_*3072];
__device__ __align__(16) __nv_bfloat16 g_qhi[BHTD_];
__device__ __align__(16) __nv_bfloat16 g_qlo[BHTD_];
__device__ __align__(16) __nv_bfloat16 g_khi[BHTD_];
__device__ __align__(16) __nv_bfloat16 g_klo[BHTD_];
__device__ __align__(16) __nv_bfloat16 g_vhi[BHTD_];
__device__ __align__(16) __nv_bfloat16 g_vlo[BHTD_];
__device__ __align__(16) __nv_bfloat16 g_vthi[BHTD_];   // [b,h,d,s]
__device__ __align__(16) __nv_bfloat16 g_vtlo[BHTD_];
__device__ __align__(16) float g_wcomb[C_*C_];
__device__ __align__(16) float g_bcomb[C_];

// ------------------------------ helpers -------------------------------------
__device__ __forceinline__ uint32_t smem_u32(const void* p) {
    uint32_t a;
    asm("{ .reg .u64 t; cvta.to.shared.u64 t, %1; cvt.u32.u64 %0, t; }"
        : "=r"(a) : "l"(p));
    return a;
}
__device__ __forceinline__ void mma_bf16(float* c, const uint32_t* a,
                                         uint32_t b0, uint32_t b1) {
    asm volatile(
        "mma.sync.aligned.m16n8k16.row.col.f32.bf16.bf16.f32 "
        "{%0,%1,%2,%3}, {%4,%5,%6,%7}, {%8,%9}, {%0,%1,%2,%3};"
        : "+f"(c[0]), "+f"(c[1]), "+f"(c[2]), "+f"(c[3])
        : "r"(a[0]), "r"(a[1]), "r"(a[2]), "r"(a[3]), "r"(b0), "r"(b1));
}
__device__ __forceinline__ uint32_t lds32(uint32_t a) {
    uint32_t v;
    asm volatile("ld.shared.b32 %0, [%1];" : "=r"(v) : "r"(a));
    return v;
}
__device__ __forceinline__ void lds128(uint32_t a, uint32_t& x, uint32_t& y,
                                       uint32_t& z, uint32_t& w) {
    asm volatile("ld.shared.v4.b32 {%0,%1,%2,%3}, [%4];"
                 : "=r"(x), "=r"(y), "=r"(z), "=r"(w) : "r"(a));
}
__device__ __forceinline__ void split_bf16(float v, __nv_bfloat16& h, __nv_bfloat16& l) {
    h = __float2bfloat16(v);
    l = __float2bfloat16(v - __bfloat162float(h));
}
__device__ __forceinline__ uint32_t pack2(float a, float b) {
    __nv_bfloat162 t = __floats2bfloat162_rn(a, b);
    return *(uint32_t*)&t;
}
__device__ __forceinline__ float resid(float v) {
    return v - __bfloat162float(__float2bfloat16(v));
}
// pack 4 fp32 (k, k+1, k+8, k+9) into one combined 16B granule
__device__ __forceinline__ void pack_granule(float f0, float f1, float f2, float f3,
                                             uint32_t* w) {
    __nv_bfloat16 h0,l0,h1,l1,h2,l2,h3,l3;
    split_bf16(f0,h0,l0); split_bf16(f1,h1,l1);
    split_bf16(f2,h2,l2); split_bf16(f3,h3,l3);
    __nv_bfloat162 t;
    t.x=h0; t.y=h1; w[0] = *(uint32_t*)&t;
    t.x=h2; t.y=h3; w[1] = *(uint32_t*)&t;
    t.x=l0; t.y=l1; w[2] = *(uint32_t*)&t;
    t.x=l2; t.y=l3; w[3] = *(uint32_t*)&t;
}

// ------------------------------ prep kernels --------------------------------
// x [BT,768] fp32 -> g_xc combined
__global__ void __launch_bounds__(256) k_prep_xc(const float* __restrict__ x) {
    int gid = blockIdx.x * 256 + threadIdx.x;   // BT*192 granules
    int lc = gid & 3, g = (gid >> 2) % 48;
    int m = gid / 192;
    const float* xr = x + (size_t)m * 768 + g * 16 + lc * 2;
    uint32_t w[4];
    pack_granule(xr[0], xr[1], xr[8], xr[9], w);
    *(uint4*)(g_xc + (size_t)m * 3072 + g * 64 + lc * 16) = *(uint4*)w;
}

// Wqkv [H,768,192] -> g_wqc combined rows n = h*192+j, k dim = c
__global__ void __launch_bounds__(256) k_prep_wqc(const float* __restrict__ W) {
    int gid = blockIdx.x * 256 + threadIdx.x;   // NQKV*192
    int lc = gid & 3, g = (gid >> 2) % 48;
    int n = gid / 192;
    int h = n / 192, j = n % 192;
    const float* wb = W + ((size_t)h * 768 + g * 16 + lc * 2) * 192 + j;
    uint32_t w[4];
    pack_granule(wb[0], wb[192], wb[8*192], wb[9*192], w);
    *(uint4*)(g_wqc + (size_t)n * 3072 + g * 64 + lc * 16) = *(uint4*)w;
}

// g_wcomb [768(k),768(n)] -> g_wcc combined rows n, k dim
__global__ void __launch_bounds__(256) k_prep_wccT() {
    int gid = blockIdx.x * 256 + threadIdx.x;   // 768*192
    int lc = gid & 3, g = (gid >> 2) % 48;
    int n = gid / 192;
    int k0 = g * 16 + lc * 2;
    uint32_t w[4];
    pack_granule(g_wcomb[(size_t)k0*768 + n],     g_wcomb[(size_t)(k0+1)*768 + n],
                 g_wcomb[(size_t)(k0+8)*768 + n], g_wcomb[(size_t)(k0+9)*768 + n], w);
    *(uint4*)(g_wcc + (size_t)n * 3072 + g * 64 + lc * 16) = *(uint4*)w;
}

__global__ void __launch_bounds__(256) k_binit(const float* __restrict__ bproj) {
    int c = blockIdx.x * 256 + threadIdx.x;
    if (c < C_) g_bcomb[c] = bproj[c];
}

__global__ void __launch_bounds__(256) k_bcomb(const float* __restrict__ bph,
                                               const float* __restrict__ Wproj) {
    int r0 = blockIdx.x * 128;
    int t = threadIdx.x;
    float a0 = 0.f, a1 = 0.f, a2 = 0.f;
    for (int rr = 0; rr < 128; ++rr) {
        int r = r0 + rr;
        float bv = bph[r];
        const float* wr = Wproj + (size_t)r * C_;
        a0 = fmaf(bv, wr[t],       a0);
        a1 = fmaf(bv, wr[t + 256], a1);
        a2 = fmaf(bv, wr[t + 512], a2);
    }
    atomicAdd(&g_bcomb[t],       a0);
    atomicAdd(&g_bcomb[t + 256], a1);
    atomicAdd(&g_bcomb[t + 512], a2);
}

// ----------------- small fp32 SGEMM (Wcomb precompute only) -----------------
__global__ void __launch_bounds__(256) sgemm64(
    const float* __restrict__ A, const float* __restrict__ Bm,
    float* __restrict__ Cm, int M, int N, int K,
    long long sA, long long sB, long long sC)
{
    __shared__ float As[16][68];
    __shared__ float Bs[16][68];
    const float* Ab = A  + (size_t)blockIdx.z * sA;
    const float* Bb = Bm + (size_t)blockIdx.z * sB;
    float*       Cb = Cm + (size_t)blockIdx.z * sC;
    const int tid = threadIdx.x;
    const int tx = tid % 16, ty = tid / 16;
    const int m0 = blockIdx.x * 64, n0 = blockIdx.y * 64;
    float acc[4][4] = {};
    for (int kt = 0; kt < K; kt += 16) {
        {
            int m = tid / 4, kq = (tid % 4) * 4;
            float4 v = *(const float4*)(Ab + (size_t)(m0+m)*K + kt + kq);
            As[kq+0][m] = v.x; As[kq+1][m] = v.y; As[kq+2][m] = v.z; As[kq+3][m] = v.w;
        }
        {
            int kk = tid / 16, nn = (tid % 16) * 4;
            *(float4*)&Bs[kk][nn] = *(const float4*)(Bb + (size_t)(kt+kk)*N + n0 + nn);
        }
        __syncthreads();
        #pragma unroll
        for (int k = 0; k < 16; ++k) {
            float a[4], b[4];
            #pragma unroll
            for (int i = 0; i < 4; ++i) a[i] = As[k][ty*4+i];
            *(float4*)b = *(const float4*)&Bs[k][tx*4];
            #pragma unroll
            for (int i = 0; i < 4; ++i)
                #pragma unroll
                for (int j = 0; j < 4; ++j)
                    acc[i][j] = fmaf(a[i], b[j], acc[i][j]);
        }
        __syncthreads();
    }
    #pragma unroll
    for (int i = 0; i < 4; ++i) {
        int m = m0 + ty*4 + i;
        #pragma unroll
        for (int j = 0; j < 4; ++j)
            Cb[(size_t)m*N + n0 + tx*4 + j] = acc[i][j];
    }
}

// ------------------- HMMA bf16-split GEMM (combined v4 layout) --------------
#define CSTR 192
#define CTILE (128*CSTR)      // 24576
#define CSTAGE (2*CTILE)      // 49152
#define HM_SMEM (2*CSTAGE)    // 98304

template<int EPI>
__global__ void __launch_bounds__(256, 2) hmma_gemm(
    const uint8_t* __restrict__ Ac, const uint8_t* __restrict__ Bc,
    float* __restrict__ Cout, const float* __restrict__ bias)
{
    extern __shared__ char smem[];
    const uint32_t sbase = smem_u32(smem);
    const int tid = threadIdx.x;
    const int wid = tid >> 5, ln = tid & 31;
    const int n0 = blockIdx.x * 128, m0 = blockIdx.y * 128;
    const int wm = wid & 3, wn = wid >> 2;
    const int mrow = wm * 32, ncol = wn * 64;
    const int lr = ln >> 2, lc = ln & 3;

    const uint8_t* gA = Ac + (size_t)m0 * 3072;
    const uint8_t* gB = Bc + (size_t)n0 * 3072;

    auto load_chunk = [&](int kc, int stage) {
        uint32_t sb = sbase + stage * CSTAGE;
        const uint8_t* pA = gA + kc * 128;
        const uint8_t* pB = gB + kc * 128;
        #pragma unroll
        for (int i = 0; i < 4; ++i) {
            int gid = tid + i * 256;
            int r = gid >> 3, c = gid & 7;
            asm volatile("cp.async.cg.shared.global [%0], [%1], 16;"
                :: "r"(sb + r*CSTR + c*16), "l"(pA + (size_t)r*3072 + c*16));
        }
        #pragma unroll
        for (int i = 0; i < 4; ++i) {
            int gid = tid + i * 256;
            int r = gid >> 3, c = gid & 7;
            asm volatile("cp.async.cg.shared.global [%0], [%1], 16;"
                :: "r"(sb + CTILE + r*CSTR + c*16), "l"(pB + (size_t)r*3072 + c*16));
        }
        asm volatile("cp.async.commit_group;");
    };

    float acc[2][8][4] = {};
    load_chunk(0, 0);
    for (int c = 0; c < 24; ++c) {
        int s = c & 1;
        asm volatile("cp.async.wait_group 0;");
        __syncthreads();
        if (c + 1 < 24) load_chunk(c + 1, s ^ 1);

        uint32_t sA = sbase + s * CSTAGE;
        uint32_t sB = sA + CTILE;

        #pragma unroll
        for (int ks = 0; ks < 2; ++ks) {
            uint32_t aH[2][4], aL[2][4];
            #pragma unroll
            for (int mt = 0; mt < 2; ++mt) {
                uint32_t base = sA + (uint32_t)((mrow + mt*16 + lr)*CSTR + ks*64 + lc*16);
                uint32_t x0,y0,z0,w0, x1,y1,z1,w1;
                lds128(base,          x0,y0,z0,w0);
                lds128(base + 8*CSTR, x1,y1,z1,w1);
                aH[mt][0]=x0; aH[mt][1]=x1; aH[mt][2]=y0; aH[mt][3]=y1;
                aL[mt][0]=z0; aL[mt][1]=z1; aL[mt][2]=w0; aL[mt][3]=w1;
            }
            #pragma unroll
            for (int nt = 0; nt < 8; ++nt) {
                uint32_t bb = sB + (uint32_t)((ncol + nt*8 + lr)*CSTR + ks*64 + lc*16);
                uint32_t bh0,bh1,bl0,bl1;
                lds128(bb, bh0,bh1,bl0,bl1);
                #pragma unroll
                for (int mt = 0; mt < 2; ++mt) {
                    mma_bf16(acc[mt][nt], aH[mt], bh0, bh1);
                    mma_bf16(acc[mt][nt], aH[mt], bl0, bl1);
                    mma_bf16(acc[mt][nt], aL[mt], bh0, bh1);
                }
            }
        }
        __syncthreads();
    }

    // ------------------------------- epilogue --------------------------------
    #pragma unroll
    for (int mt = 0; mt < 2; ++mt) {
        int m = m0 + mrow + mt*16 + lr;
        #pragma unroll
        for (int nt = 0; nt < 8; ++nt) {
            int n = n0 + ncol + nt*8 + lc*2;
            float b0 = bias[n], b1 = bias[n+1];
            float* ac = acc[mt][nt];
            if (EPI == 0) {
                float2 v0 = {ac[0] + b0, ac[1] + b1};
                float2 v1 = {ac[2] + b0, ac[3] + b1};
                *(float2*)(Cout + (size_t)m * C_ + n) = v0;
                *(float2*)(Cout + (size_t)(m+8) * C_ + n) = v1;
            } else {
                int h = n / 192, r = n % 192;
                int blk = r >> 6, roff = r & 63;
                float sc = (blk == 0) ? QSCALE : 1.0f;
                __nv_bfloat16* dhi = (blk == 0) ? g_qhi : ((blk == 1) ? g_khi : g_vhi);
                __nv_bfloat16* dlo = (blk == 0) ? g_qlo : ((blk == 1) ? g_klo : g_vlo);
                #pragma unroll
                for (int rr = 0; rr < 2; ++rr) {
                    int mm = m + rr*8;
                    int b_ = mm >> 9, t_ = mm & 511;
                    size_t o = (((size_t)b_ * H_ + h) * T_ + t_) * 64 + roff;
                    float v0 = (ac[rr*2+0] + b0) * sc;
                    float v1 = (ac[rr*2+1] + b1) * sc;
                    __nv_bfloat16 h0,h1,l0,l1;
                    split_bf16(v0,h0,l0); split_bf16(v1,h1,l1);
                    __nv_bfloat162 ph; ph.x=h0; ph.y=h1;
                    __nv_bfloat162 pl; pl.x=l0; pl.y=l1;
                    *(__nv_bfloat162*)(dhi + o) = ph;
                    *(__nv_bfloat162*)(dlo + o) = pl;
                }
            }
        }
    }
}

// ------------------------ V transpose: [s][d] -> [d][s] ----------------------
__global__ void __launch_bounds__(256) k_vT() {
    __shared__ __nv_bfloat16 thi[64][72];
    __shared__ __nv_bfloat16 tlo[64][72];
    const int s0 = blockIdx.x * 64;
    const int bh = blockIdx.y;
    const int tid = threadIdx.x;
    const int r = tid >> 2, cs = (tid & 3) * 16;
    const size_t sbase = ((size_t)bh * T_ + s0 + r) * 64 + cs;
    #pragma unroll
    for (int j = 0; j < 2; ++j) {
        *(uint4*)&thi[r][cs + j*8] = *(const uint4*)(g_vhi + sbase + j*8);
        *(uint4*)&tlo[r][cs + j*8] = *(const uint4*)(g_vlo + sbase + j*8);
    }
    __syncthreads();
    const int d = tid >> 2, ss = (tid & 3) * 16;
    const size_t dbase = ((size_t)bh * 64 + d) * T_ + s0 + ss;
    #pragma unroll
    for (int j = 0; j < 2; ++j) {
        uint32_t ph[4], pl[4];
        #pragma unroll
        for (int q = 0; q < 4; ++q) {
            int s = ss + j*8 + q*2;
            __nv_bfloat162 a; a.x = thi[s][d]; a.y = thi[s+1][d];
            ph[q] = *(uint32_t*)&a;
            __nv_bfloat162 b2; b2.x = tlo[s][d]; b2.y = tlo[s+1][d];
            pl[q] = *(uint32_t*)&b2;
        }
        *(uint4*)(g_vthi + dbase + j*8) = *(uint4*)ph;
        *(uint4*)(g_vtlo + dbase + j*8) = *(uint4*)pl;
    }
}

// --------------------------- HMMA fused attention ----------------------------
#define KSTR 144u
#define QSTR 144u
#define VTSTR 1040u
#define SM_K 0u
#define SM_KLO 73728u
#define SM_VT 0u
#define SM_VTLO 66560u
#define SM_Q 147456u
#define SM_QLO 156672u
#define SM_OBUF 147456u
#define OSTRF 72
#define SM_EXM 165888u
#define SM_EXS 166912u
#define ATTN_SMEM 167936

__global__ void __launch_bounds__(512) attn_k(float* __restrict__ probs)
{
    extern __shared__ char smem[];
    const uint32_t sb = smem_u32(smem);
    const int tid = threadIdx.x;
    const int wid = tid >> 5, ln = tid & 31;
    const int wm = wid & 3, wq = wid >> 2;
    const int b = blockIdx.z, h = blockIdx.y, t0 = blockIdx.x * 64;
    const int bh = b * H_ + h;
    const int lr = ln >> 2, lc = ln & 3;

    // ---- load K (full 512) + Q (64 rows), hi/lo ----
    {
        const __nv_bfloat16* khi = g_khi + (size_t)bh * T_ * 64;
        const __nv_bfloat16* klo = g_klo + (size_t)bh * T_ * 64;
        #pragma unroll
        for (int i = 0; i < 8; ++i) {
            int idx = tid + i * 512;
            int r = idx >> 3, sg = idx & 7;
            asm volatile("cp.async.cg.shared.global [%0], [%1], 16;"
                :: "r"(sb + SM_K + r*KSTR + sg*16), "l"(khi + (size_t)r*64 + sg*8));
        }
        #pragma unroll
        for (int i = 0; i < 8; ++i) {
            int idx = tid + i * 512;
            int r = idx >> 3, sg = idx & 7;
            asm volatile("cp.async.cg.shared.global [%0], [%1], 16;"
                :: "r"(sb + SM_KLO + r*KSTR + sg*16), "l"(klo + (size_t)r*64 + sg*8));
        }
        const __nv_bfloat16* qhi = g_qhi + ((size_t)bh * T_ + t0) * 64;
        const __nv_bfloat16* qlo = g_qlo + ((size_t)bh * T_ + t0) * 64;
        {
            int r = tid >> 3, sg = tid & 7;
            asm volatile("cp.async.cg.shared.global [%0], [%1], 16;"
                :: "r"(sb + SM_Q + r*QSTR + sg*16), "l"(qhi + (size_t)r*64 + sg*8));
            asm volatile("cp.async.cg.shared.global [%0], [%1], 16;"
                :: "r"(sb + SM_QLO + r*QSTR + sg*16), "l"(qlo + (size_t)r*64 + sg*8));
        }
        asm volatile("cp.async.commit_group;");
        asm volatile("cp.async.wait_group 0;");
    }
    __syncthreads();

    // ---- Q fragments ----
    uint32_t aH[4][4], aL[4][4];
    {
        const int row = wm * 16 + lr;
        #pragma unroll
        for (int ks = 0; ks < 4; ++ks) {
            uint32_t off = row * QSTR + ks * 32 + lc * 4;
            aH[ks][0] = lds32(sb + SM_Q + off);
            aH[ks][1] = lds32(sb + SM_Q + off + 8*QSTR);
            aH[ks][2] = lds32(sb + SM_Q + off + 16);
            aH[ks][3] = lds32(sb + SM_Q + off + 8*QSTR + 16);
            aL[ks][0] = lds32(sb + SM_QLO + off);
            aL[ks][1] = lds32(sb + SM_QLO + off + 8*QSTR);
            aL[ks][2] = lds32(sb + SM_QLO + off + 16);
            aL[ks][3] = lds32(sb + SM_QLO + off + 8*QSTR + 16);
        }
    }

    // ---- S = Q K^T ----
    float acc[16][4];
    #pragma unroll
    for (int nt = 0; nt < 16; ++nt) { acc[nt][0]=acc[nt][1]=acc[nt][2]=acc[nt][3]=0.f; }
    #pragma unroll
    for (int nt = 0; nt < 16; ++nt) {
        uint32_t krow = (uint32_t)(wq * 128 + nt * 8 + lr);
        #pragma unroll
        for (int ks = 0; ks < 4; ++ks) {
            uint32_t boff = krow * KSTR + ks * 32 + lc * 4;
            uint32_t bh0 = lds32(sb + SM_K + boff);
            uint32_t bh1 = lds32(sb + SM_K + boff + 16);
            uint32_t bl0 = lds32(sb + SM_KLO + boff);
            uint32_t bl1 = lds32(sb + SM_KLO + boff + 16);
            mma_bf16(acc[nt], aH[ks], bh0, bh1);
            mma_bf16(acc[nt], aH[ks], bl0, bl1);
            mma_bf16(acc[nt], aL[ks], bh0, bh1);
        }
    }

    // ---- softmax over 512 keys ----
    const int row0 = wm * 16 + lr;
    {
        float mx0 = -1e30f, mx1 = -1e30f;
        #pragma unroll
        for (int nt = 0; nt < 16; ++nt) {
            mx0 = fmaxf(mx0, fmaxf(acc[nt][0], acc[nt][1]));
            mx1 = fmaxf(mx1, fmaxf(acc[nt][2], acc[nt][3]));
        }
        mx0 = fmaxf(mx0, __shfl_xor_sync(0xffffffffu, mx0, 1));
        mx0 = fmaxf(mx0, __shfl_xor_sync(0xffffffffu, mx0, 2));
        mx1 = fmaxf(mx1, __shfl_xor_sync(0xffffffffu, mx1, 1));
        mx1 = fmaxf(mx1, __shfl_xor_sync(0xffffffffu, mx1, 2));
        float* exm = (float*)(smem + SM_EXM);
        if (lc == 0) { exm[wq*64 + row0] = mx0; exm[wq*64 + row0 + 8] = mx1; }
        __syncthreads();     // all warps past S MMAs -> K region dead

        // ---- prefetch VT into K region (overlaps softmax + probs write) ----
        {
            const __nv_bfloat16* vthi = g_vthi + (size_t)bh * 64 * T_;
            const __nv_bfloat16* vtlo = g_vtlo + (size_t)bh * 64 * T_;
            #pragma unroll
            for (int i = 0; i < 8; ++i) {
                int idx = tid + i * 512;
                int d = idx >> 6, sg = idx & 63;
                asm volatile("cp.async.cg.shared.global [%0], [%1], 16;"
                    :: "r"(sb + SM_VT + d*VTSTR + sg*16), "l"(vthi + (size_t)d*T_ + sg*8));
            }
            #pragma unroll
            for (int i = 0; i < 8; ++i) {
                int idx = tid + i * 512;
                int d = idx >> 6, sg = idx & 63;
                asm volatile("cp.async.cg.shared.global [%0], [%1], 16;"
                    :: "r"(sb + SM_VTLO + d*VTSTR + sg*16), "l"(vtlo + (size_t)d*T_ + sg*8));
            }
            asm volatile("cp.async.commit_group;");
        }

        float m0 = fmaxf(fmaxf(exm[row0],      exm[64+row0]),
                         fmaxf(exm[128+row0],  exm[192+row0]));
        float m1 = fmaxf(fmaxf(exm[row0+8],    exm[64+row0+8]),
                         fmaxf(exm[128+row0+8],exm[192+row0+8]));
        float s0 = 0.f, s1 = 0.f;
        #pragma unroll
        for (int nt = 0; nt < 16; ++nt) {
            acc[nt][0] = __expf(acc[nt][0] - m0); s0 += acc[nt][0];
            acc[nt][1] = __expf(acc[nt][1] - m0); s0 += acc[nt][1];
            acc[nt][2] = __expf(acc[nt][2] - m1); s1 += acc[nt][2];
            acc[nt][3] = __expf(acc[nt][3] - m1); s1 += acc[nt][3];
        }
        s0 += __shfl_xor_sync(0xffffffffu, s0, 1);
        s0 += __shfl_xor_sync(0xffffffffu, s0, 2);
        s1 += __shfl_xor_sync(0xffffffffu, s1, 1);
        s1 += __shfl_xor_sync(0xffffffffu, s1, 2);
        float* exs = (float*)(smem + SM_EXS);
        if (lc == 0) { exs[wq*64 + row0] = s0; exs[wq*64 + row0 + 8] = s1; }
        __syncthreads();
        float inv0 = 1.0f / (exs[row0] + exs[64+row0] + exs[128+row0] + exs[192+row0]);
        float inv1 = 1.0f / (exs[row0+8] + exs[64+row0+8] + exs[128+row0+8] + exs[192+row0+8]);
        #pragma unroll
        for (int nt = 0; nt < 16; ++nt) {
            acc[nt][0] *= inv0; acc[nt][1] *= inv0;
            acc[nt][2] *= inv1; acc[nt][3] *= inv1;
        }
    }

    // ---- write probs ----
    {
        float* p0 = probs + ((size_t)bh * T_ + t0 + row0) * 512 + wq*128 + lc*2;
        float* p1 = p0 + (size_t)8 * 512;
        #pragma unroll
        for (int nt = 0; nt < 16; ++nt) {
            float2 v0 = {acc[nt][0], acc[nt][1]};
            float2 v1 = {acc[nt][2], acc[nt][3]};
            *(float2*)(p0 + nt*8) = v0;
            *(float2*)(p1 + nt*8) = v1;
        }
    }

    // ---- wait VT, then PV ----
    asm volatile("cp.async.wait_group 0;");
    __syncthreads();

    float oacc[8][4];
    #pragma unroll
    for (int dn = 0; dn < 8; ++dn) { oacc[dn][0]=oacc[dn][1]=oacc[dn][2]=oacc[dn][3]=0.f; }
    #pragma unroll
    for (int kk = 0; kk < 8; ++kk) {
        uint32_t phi[4], plo[4];
        phi[0] = pack2(acc[2*kk][0],   acc[2*kk][1]);
        phi[1] = pack2(acc[2*kk][2],   acc[2*kk][3]);
        phi[2] = pack2(acc[2*kk+1][0], acc[2*kk+1][1]);
        phi[3] = pack2(acc[2*kk+1][2], acc[2*kk+1][3]);
        plo[0] = pack2(resid(acc[2*kk][0]),   resid(acc[2*kk][1]));
        plo[1] = pack2(resid(acc[2*kk][2]),   resid(acc[2*kk][3]));
        plo[2] = pack2(resid(acc[2*kk+1][0]), resid(acc[2*kk+1][1]));
        plo[3] = pack2(resid(acc[2*kk+1][2]), resid(acc[2*kk+1][3]));
        uint32_t colV = (uint32_t)((wq*128 + kk*16 + lc*2) * 2);
        #pragma unroll
        for (int dn = 0; dn < 8; ++dn) {
            uint32_t vrow = (uint32_t)(dn*8 + lr);
            uint32_t offH = vrow * VTSTR + colV;
            uint32_t bh0 = lds32(sb + SM_VT + offH);
            uint32_t bh1 = lds32(sb + SM_VT + offH + 16);
            uint32_t bl0 = lds32(sb + SM_VTLO + offH);
            uint32_t bl1 = lds32(sb + SM_VTLO + offH + 16);
            mma_bf16(oacc[dn], phi, bh0, bh1);
            mma_bf16(oacc[dn], phi, bl0, bl1);
            mma_bf16(oacc[dn], plo, bh0, bh1);
        }
    }

    // ---- cross-warp reduce ----
    float* obuf = (float*)(smem + SM_OBUF);
    #pragma unroll
    for (int g = 0; g < 4; ++g) {
        if (wq == g) {
            #pragma unroll
            for (int dn = 0; dn < 8; ++dn) {
                int c = dn*8 + lc*2;
                float* b0 = obuf + row0 * OSTRF + c;
                float* b1 = obuf + (row0 + 8) * OSTRF + c;
                if (g == 0) {
                    b0[0] = oacc[dn][0]; b0[1] = oacc[dn][1];
                    b1[0] = oacc[dn][2]; b1[1] = oacc[dn][3];
                } else {
                    b0[0] += oacc[dn][0]; b0[1] += oacc[dn][1];
                    b1[0] += oacc[dn][2]; b1[1] += oacc[dn][3];
                }
            }
        }
        __syncthreads();
    }

    // ---- write O in combined layout for OUT gemm ----
    {
        int row = tid >> 3, s2 = tid & 7;
        const float* src = obuf + row * OSTRF;
        size_t rb = ((size_t)b * T_ + t0 + row) * 3072 + (size_t)h * 256;
        #pragma unroll
        for (int u = 0; u < 2; ++u) {
            int s = s2 * 2 + u;
            int g = s >> 2, lcx = s & 3;
            int k0 = g * 16 + lcx * 2;
            uint32_t w[4];
            pack_granule(src[k0], src[k0+1], src[k0+8], src[k0+9], w);
            *(uint4*)(g_oc + rb + g*64 + lcx*16) = *(uint4*)w;
        }
    }
}

// --------------------------------- launcher ---------------------------------
extern "C" void kernel_launch(void* const* d_in, const int* in_sizes, int n_in,
                              void* d_out, int out_size)
{
    const float* x     = (const float*)d_in[0];
    const float* Wqkv  = (const float*)d_in[1];
    const float* bqkv  = (const float*)d_in[2];
    const float* Wph   = (const float*)d_in[3];
    const float* bph   = (const float*)d_in[4];
    const float* Wproj = (const float*)d_in[5];
    const float* bproj = (const float*)d_in[6];
    float* out = (float*)d_out;
    float* sa_out = out;
    float* probs  = out + (size_t)BT_*C_;

    uint8_t *xc_p, *wqc_p, *oc_p, *wcc_p;
    float *wcomb_p, *bcomb_p;
    cudaGetSymbolAddress((void**)&xc_p,   g_xc);
    cudaGetSymbolAddress((void**)&wqc_p,  g_wqc);
    cudaGetSymbolAddress((void**)&oc_p,   g_oc);
    cudaGetSymbolAddress((void**)&wcc_p,  g_wcc);
    cudaGetSymbolAddress((void**)&wcomb_p, g_wcomb);
    cudaGetSymbolAddress((void**)&bcomb_p, g_bcomb);

    static int attrs_set = 0;
    if (!attrs_set) {
        cudaFuncSetAttribute(hmma_gemm<0>, cudaFuncAttributeMaxDynamicSharedMemorySize, HM_SMEM);
        cudaFuncSetAttribute(hmma_gemm<1>, cudaFuncAttributeMaxDynamicSharedMemorySize, HM_SMEM);
        cudaFuncSetAttribute(attn_k, cudaFuncAttributeMaxDynamicSharedMemorySize, ATTN_SMEM);
        attrs_set = 1;
    }

    // 1-3: prep on QKV critical path (+ tiny binit)
    k_prep_xc<<<BT_*192/256, 256>>>(x);
    k_prep_wqc<<<NQKV_*192/256, 256>>>(Wqkv);
    k_binit<<<3, 256>>>(bproj);

    // 4: QKV GEMM (profiled slot) -> q/k/v bf16 hi/lo
    hmma_gemm<1><<<dim3(NQKV_/128, BT_/128), 256, HM_SMEM>>>(
        xc_p, wqc_p, nullptr, bqkv);

    // 5-7: Wcomb chain (independent of attention)
    k_bcomb<<<72, 256>>>(bph, Wproj);
    sgemm64<<<dim3(1,12,12), 256>>>(Wph, Wproj, wcomb_p,
        64, C_, C_, (long long)64*C_, (long long)C_*C_, (long long)64*C_);
    k_prep_wccT<<<C_*192/256, 256>>>();

    // 8: V transpose
    k_vT<<<dim3(T_/64, B_*H_), 256>>>();

    // 9: fused attention -> probs + O(combined)
    attn_k<<<dim3(T_/64, H_, B_), 512, ATTN_SMEM>>>(probs);

    // 10: output GEMM + bcomb -> sa_out
    hmma_gemm<0><<<dim3(C_/128, BT_/128), 256, HM_SMEM>>>(
        oc_p, wcc_p, sa_out, bcomb_p);
}

// round 7
// speedup vs baseline: 3.3947x; 1.0210x over previous
#include <cuda_runtime.h>
#include <cuda_bf16.h>
#include <stdint.h>
#include <math.h>

#define H_   12
#define T_   512
#define D_   64
#define C_   768
#define B_   32
#define NQKV_ 2304
#define BT_  16384
#define BHTD_ ((size_t)B_*H_*T_*D_)
#define QSCALE 0.125f

// ------------- device-global scratch (no runtime alloc allowed) -------------
__device__ __align__(16) uint8_t g_xc[(size_t)BT_*3072];
__device__ __align__(16) uint8_t g_wqc[(size_t)NQKV_*3072];
__device__ __align__(16) uint8_t g_oc[(size_t)BT_*3072];
__device__ __align__(16) uint8_t g_wcc[(size_t)C_*3072];
__device__ __align__(16) __nv_bfloat16 g_qhi[BHTD_];
__device__ __align__(16) __nv_bfloat16 g_qlo[BHTD_];
__device__ __align__(16) __nv_bfloat16 g_khi[BHTD_];
__device__ __align__(16) __nv_bfloat16 g_klo[BHTD_];
__device__ __align__(16) __nv_bfloat16 g_vhi[BHTD_];
__device__ __align__(16) __nv_bfloat16 g_vlo[BHTD_];
__device__ __align__(16) __nv_bfloat16 g_vthi[BHTD_];   // [b,h,d,s]
__device__ __align__(16) __nv_bfloat16 g_vtlo[BHTD_];
__device__ __align__(16) float g_wcomb[C_*C_];
__device__ __align__(16) float g_bcomb[C_];

// ------------------------------ helpers -------------------------------------
__device__ __forceinline__ uint32_t smem_u32(const void* p) {
    uint32_t a;
    asm("{ .reg .u64 t; cvta.to.shared.u64 t, %1; cvt.u32.u64 %0, t; }"
        : "=r"(a) : "l"(p));
    return a;
}
__device__ __forceinline__ void mma_bf16(float* c, const uint32_t* a,
                                         uint32_t b0, uint32_t b1) {
    asm volatile(
        "mma.sync.aligned.m16n8k16.row.col.f32.bf16.bf16.f32 "
        "{%0,%1,%2,%3}, {%4,%5,%6,%7}, {%8,%9}, {%0,%1,%2,%3};"
        : "+f"(c[0]), "+f"(c[1]), "+f"(c[2]), "+f"(c[3])
        : "r"(a[0]), "r"(a[1]), "r"(a[2]), "r"(a[3]), "r"(b0), "r"(b1));
}
__device__ __forceinline__ uint32_t lds32(uint32_t a) {
    uint32_t v;
    asm volatile("ld.shared.b32 %0, [%1];" : "=r"(v) : "r"(a));
    return v;
}
__device__ __forceinline__ void lds128(uint32_t a, uint32_t& x, uint32_t& y,
                                       uint32_t& z, uint32_t& w) {
    asm volatile("ld.shared.v4.b32 {%0,%1,%2,%3}, [%4];"
                 : "=r"(x), "=r"(y), "=r"(z), "=r"(w) : "r"(a));
}
__device__ __forceinline__ void split_bf16(float v, __nv_bfloat16& h, __nv_bfloat16& l) {
    h = __float2bfloat16(v);
    l = __float2bfloat16(v - __bfloat162float(h));
}
__device__ __forceinline__ uint32_t pack2(float a, float b) {
    __nv_bfloat162 t = __floats2bfloat162_rn(a, b);
    return *(uint32_t*)&t;
}
__device__ __forceinline__ float resid(float v) {
    return v - __bfloat162float(__float2bfloat16(v));
}
__device__ __forceinline__ void pack_granule(float f0, float f1, float f2, float f3,
                                             uint32_t* w) {
    __nv_bfloat16 h0,l0,h1,l1,h2,l2,h3,l3;
    split_bf16(f0,h0,l0); split_bf16(f1,h1,l1);
    split_bf16(f2,h2,l2); split_bf16(f3,h3,l3);
    __nv_bfloat162 t;
    t.x=h0; t.y=h1; w[0] = *(uint32_t*)&t;
    t.x=h2; t.y=h3; w[1] = *(uint32_t*)&t;
    t.x=l0; t.y=l1; w[2] = *(uint32_t*)&t;
    t.x=l2; t.y=l3; w[3] = *(uint32_t*)&t;
}

// ------------------------------ prep kernels --------------------------------
__global__ void __launch_bounds__(256) k_prep_xc(const float* __restrict__ x) {
    int gid = blockIdx.x * 256 + threadIdx.x;
    int lc = gid & 3, g = (gid >> 2) % 48;
    int m = gid / 192;
    const float* xr = x + (size_t)m * 768 + g * 16 + lc * 2;
    uint32_t w[4];
    pack_granule(xr[0], xr[1], xr[8], xr[9], w);
    *(uint4*)(g_xc + (size_t)m * 3072 + g * 64 + lc * 16) = *(uint4*)w;
}

__global__ void __launch_bounds__(256) k_prep_wqc(const float* __restrict__ W) {
    int gid = blockIdx.x * 256 + threadIdx.x;
    int lc = gid & 3, g = (gid >> 2) % 48;
    int n = gid / 192;
    int h = n / 192, j = n % 192;
    const float* wb = W + ((size_t)h * 768 + g * 16 + lc * 2) * 192 + j;
    uint32_t w[4];
    pack_granule(wb[0], wb[192], wb[8*192], wb[9*192], w);
    *(uint4*)(g_wqc + (size_t)n * 3072 + g * 64 + lc * 16) = *(uint4*)w;
}

__global__ void __launch_bounds__(256) k_prep_wccT() {
    int gid = blockIdx.x * 256 + threadIdx.x;
    int lc = gid & 3, g = (gid >> 2) % 48;
    int n = gid / 192;
    int k0 = g * 16 + lc * 2;
    uint32_t w[4];
    pack_granule(g_wcomb[(size_t)k0*768 + n],     g_wcomb[(size_t)(k0+1)*768 + n],
                 g_wcomb[(size_t)(k0+8)*768 + n], g_wcomb[(size_t)(k0+9)*768 + n], w);
    *(uint4*)(g_wcc + (size_t)n * 3072 + g * 64 + lc * 16) = *(uint4*)w;
}

// zero g_wcomb + init g_bcomb = bproj
__global__ void __launch_bounds__(256) k_binit(const float* __restrict__ bproj) {
    int idx = blockIdx.x * 256 + threadIdx.x;
    if (idx < C_*C_) g_wcomb[idx] = 0.0f;
    int j = idx - C_*C_;
    if (j >= 0 && j < C_) g_bcomb[j] = bproj[j];
}

__global__ void __launch_bounds__(256) k_bcomb(const float* __restrict__ bph,
                                               const float* __restrict__ Wproj) {
    int r0 = blockIdx.x * 32;
    int t = threadIdx.x;
    float a0 = 0.f, a1 = 0.f, a2 = 0.f;
    for (int rr = 0; rr < 32; ++rr) {
        int r = r0 + rr;
        float bv = bph[r];
        const float* wr = Wproj + (size_t)r * C_;
        a0 = fmaf(bv, wr[t],       a0);
        a1 = fmaf(bv, wr[t + 256], a1);
        a2 = fmaf(bv, wr[t + 512], a2);
    }
    atomicAdd(&g_bcomb[t],       a0);
    atomicAdd(&g_bcomb[t + 256], a1);
    atomicAdd(&g_bcomb[t + 512], a2);
}

// ------- Wcomb precompute: fp32, 4-way K-split, atomic accumulate -----------
__global__ void __launch_bounds__(256) sgemm64ks(
    const float* __restrict__ A, const float* __restrict__ Bm,
    float* __restrict__ Cm)
{
    __shared__ float As[16][68];
    __shared__ float Bs[16][68];
    const int z = blockIdx.z;                 // head
    const float* Ab = A  + (size_t)z * 64 * C_;
    const float* Bb = Bm + (size_t)z * C_ * C_;
    float*       Cb = Cm + (size_t)z * 64 * C_;
    const int tid = threadIdx.x;
    const int tx = tid % 16, ty = tid / 16;
    const int n0 = blockIdx.y * 64;
    const int kbeg = blockIdx.x * 192, kend = kbeg + 192;
    float acc[4][4] = {};
    for (int kt = kbeg; kt < kend; kt += 16) {
        {
            int m = tid / 4, kq = (tid % 4) * 4;
            float4 v = *(const float4*)(Ab + (size_t)m*C_ + kt + kq);
            As[kq+0][m] = v.x; As[kq+1][m] = v.y; As[kq+2][m] = v.z; As[kq+3][m] = v.w;
        }
        {
            int kk = tid / 16, nn = (tid % 16) * 4;
            *(float4*)&Bs[kk][nn] = *(const float4*)(Bb + (size_t)(kt+kk)*C_ + n0 + nn);
        }
        __syncthreads();
        #pragma unroll
        for (int k = 0; k < 16; ++k) {
            float a[4], b[4];
            #pragma unroll
            for (int i = 0; i < 4; ++i) a[i] = As[k][ty*4+i];
            *(float4*)b = *(const float4*)&Bs[k][tx*4];
            #pragma unroll
            for (int i = 0; i < 4; ++i)
                #pragma unroll
                for (int j = 0; j < 4; ++j)
                    acc[i][j] = fmaf(a[i], b[j], acc[i][j]);
        }
        __syncthreads();
    }
    #pragma unroll
    for (int i = 0; i < 4; ++i) {
        int m = ty*4 + i;
        #pragma unroll
        for (int j = 0; j < 4; ++j)
            atomicAdd(&Cb[(size_t)m*C_ + n0 + tx*4 + j], acc[i][j]);
    }
}

// ------------------- HMMA bf16-split GEMM (combined v4 layout) --------------
#define CSTR 192
#define CTILE (128*CSTR)      // 24576
#define CSTAGE (2*CTILE)      // 49152
#define HM_SMEM (2*CSTAGE)    // 98304

template<int EPI>
__global__ void __launch_bounds__(256, 2) hmma_gemm(
    const uint8_t* __restrict__ Ac, const uint8_t* __restrict__ Bc,
    float* __restrict__ Cout, const float* __restrict__ bias)
{
    extern __shared__ char smem[];
    const uint32_t sbase = smem_u32(smem);
    const int tid = threadIdx.x;
    const int wid = tid >> 5, ln = tid & 31;
    const int n0 = blockIdx.x * 128, m0 = blockIdx.y * 128;
    const int wm = wid & 3, wn = wid >> 2;
    const int mrow = wm * 32, ncol = wn * 64;
    const int lr = ln >> 2, lc = ln & 3;

    const uint8_t* gA = Ac + (size_t)m0 * 3072;
    const uint8_t* gB = Bc + (size_t)n0 * 3072;

    auto load_chunk = [&](int kc, int stage) {
        uint32_t sb = sbase + stage * CSTAGE;
        const uint8_t* pA = gA + kc * 128;
        const uint8_t* pB = gB + kc * 128;
        #pragma unroll
        for (int i = 0; i < 4; ++i) {
            int gid = tid + i * 256;
            int r = gid >> 3, c = gid & 7;
            asm volatile("cp.async.cg.shared.global [%0], [%1], 16;"
                :: "r"(sb + r*CSTR + c*16), "l"(pA + (size_t)r*3072 + c*16));
        }
        #pragma unroll
        for (int i = 0; i < 4; ++i) {
            int gid = tid + i * 256;
            int r = gid >> 3, c = gid & 7;
            asm volatile("cp.async.cg.shared.global [%0], [%1], 16;"
                :: "r"(sb + CTILE + r*CSTR + c*16), "l"(pB + (size_t)r*3072 + c*16));
        }
        asm volatile("cp.async.commit_group;");
    };

    float acc[2][8][4] = {};
    load_chunk(0, 0);
    for (int c = 0; c < 24; ++c) {
        int s = c & 1;
        asm volatile("cp.async.wait_group 0;");
        __syncthreads();                 // also protects stage s^1 reuse below
        if (c + 1 < 24) load_chunk(c + 1, s ^ 1);

        uint32_t sA = sbase + s * CSTAGE;
        uint32_t sB = sA + CTILE;

        #pragma unroll
        for (int ks = 0; ks < 2; ++ks) {
            uint32_t aH[2][4], aL[2][4];
            #pragma unroll
            for (int mt = 0; mt < 2; ++mt) {
                uint32_t base = sA + (uint32_t)((mrow + mt*16 + lr)*CSTR + ks*64 + lc*16);
                uint32_t x0,y0,z0,w0, x1,y1,z1,w1;
                lds128(base,          x0,y0,z0,w0);
                lds128(base + 8*CSTR, x1,y1,z1,w1);
                aH[mt][0]=x0; aH[mt][1]=x1; aH[mt][2]=y0; aH[mt][3]=y1;
                aL[mt][0]=z0; aL[mt][1]=z1; aL[mt][2]=w0; aL[mt][3]=w1;
            }
            // register double-buffered B fragments
            uint32_t bc[4], bn[4];
            uint32_t bb0 = sB + (uint32_t)((ncol + lr)*CSTR + ks*64 + lc*16);
            lds128(bb0, bc[0], bc[1], bc[2], bc[3]);
            #pragma unroll
            for (int nt = 0; nt < 8; ++nt) {
                if (nt < 7) {
                    uint32_t bb = sB + (uint32_t)((ncol + (nt+1)*8 + lr)*CSTR + ks*64 + lc*16);
                    lds128(bb, bn[0], bn[1], bn[2], bn[3]);
                }
                #pragma unroll
                for (int mt = 0; mt < 2; ++mt) {
                    mma_bf16(acc[mt][nt], aH[mt], bc[0], bc[1]);
                    mma_bf16(acc[mt][nt], aH[mt], bc[2], bc[3]);
                    mma_bf16(acc[mt][nt], aL[mt], bc[0], bc[1]);
                }
                if (nt < 7) { bc[0]=bn[0]; bc[1]=bn[1]; bc[2]=bn[2]; bc[3]=bn[3]; }
            }
        }
        // no trailing sync: next iteration's barrier protects buffer reuse
    }

    // ------------------------------- epilogue --------------------------------
    #pragma unroll
    for (int mt = 0; mt < 2; ++mt) {
        int m = m0 + mrow + mt*16 + lr;
        #pragma unroll
        for (int nt = 0; nt < 8; ++nt) {
            int n = n0 + ncol + nt*8 + lc*2;
            float b0 = bias[n], b1 = bias[n+1];
            float* ac = acc[mt][nt];
            if (EPI == 0) {
                float2 v0 = {ac[0] + b0, ac[1] + b1};
                float2 v1 = {ac[2] + b0, ac[3] + b1};
                *(float2*)(Cout + (size_t)m * C_ + n) = v0;
                *(float2*)(Cout + (size_t)(m+8) * C_ + n) = v1;
            } else {
                int h = n / 192, r = n % 192;
                int blk = r >> 6, roff = r & 63;
                float sc = (blk == 0) ? QSCALE : 1.0f;
                __nv_bfloat16* dhi = (blk == 0) ? g_qhi : ((blk == 1) ? g_khi : g_vhi);
                __nv_bfloat16* dlo = (blk == 0) ? g_qlo : ((blk == 1) ? g_klo : g_vlo);
                #pragma unroll
                for (int rr = 0; rr < 2; ++rr) {
                    int mm = m + rr*8;
                    int b_ = mm >> 9, t_ = mm & 511;
                    size_t o = (((size_t)b_ * H_ + h) * T_ + t_) * 64 + roff;
                    float v0 = (ac[rr*2+0] + b0) * sc;
                    float v1 = (ac[rr*2+1] + b1) * sc;
                    __nv_bfloat16 h0,h1,l0,l1;
                    split_bf16(v0,h0,l0); split_bf16(v1,h1,l1);
                    __nv_bfloat162 ph; ph.x=h0; ph.y=h1;
                    __nv_bfloat162 pl; pl.x=l0; pl.y=l1;
                    *(__nv_bfloat162*)(dhi + o) = ph;
                    *(__nv_bfloat162*)(dlo + o) = pl;
                }
            }
        }
    }
}

// ------------------------ V transpose: [s][d] -> [d][s] ----------------------
__global__ void __launch_bounds__(256) k_vT() {
    __shared__ __nv_bfloat16 thi[64][72];
    __shared__ __nv_bfloat16 tlo[64][72];
    const int s0 = blockIdx.x * 64;
    const int bh = blockIdx.y;
    const int tid = threadIdx.x;
    const int r = tid >> 2, cs = (tid & 3) * 16;
    const size_t sbase = ((size_t)bh * T_ + s0 + r) * 64 + cs;
    #pragma unroll
    for (int j = 0; j < 2; ++j) {
        *(uint4*)&thi[r][cs + j*8] = *(const uint4*)(g_vhi + sbase + j*8);
        *(uint4*)&tlo[r][cs + j*8] = *(const uint4*)(g_vlo + sbase + j*8);
    }
    __syncthreads();
    const int d = tid >> 2, ss = (tid & 3) * 16;
    const size_t dbase = ((size_t)bh * 64 + d) * T_ + s0 + ss;
    #pragma unroll
    for (int j = 0; j < 2; ++j) {
        uint32_t ph[4], pl[4];
        #pragma unroll
        for (int q = 0; q < 4; ++q) {
            int s = ss + j*8 + q*2;
            __nv_bfloat162 a; a.x = thi[s][d]; a.y = thi[s+1][d];
            ph[q] = *(uint32_t*)&a;
            __nv_bfloat162 b2; b2.x = tlo[s][d]; b2.y = tlo[s+1][d];
            pl[q] = *(uint32_t*)&b2;
        }
        *(uint4*)(g_vthi + dbase + j*8) = *(uint4*)ph;
        *(uint4*)(g_vtlo + dbase + j*8) = *(uint4*)pl;
    }
}

// --------------------------- HMMA fused attention ----------------------------
#define KSTR 144u
#define QSTR 144u
#define VTSTR 1040u
#define SM_K 0u
#define SM_KLO 73728u
#define SM_VT 0u
#define SM_VTLO 66560u
#define SM_Q 147456u
#define SM_QLO 156672u
#define SM_OBUF 147456u
#define OSTRF 72
#define SM_EXM 165888u
#define SM_EXS 166912u
#define ATTN_SMEM 167936

__global__ void __launch_bounds__(512) attn_k(float* __restrict__ probs)
{
    extern __shared__ char smem[];
    const uint32_t sb = smem_u32(smem);
    const int tid = threadIdx.x;
    const int wid = tid >> 5, ln = tid & 31;
    const int wm = wid & 3, wq = wid >> 2;
    const int b = blockIdx.z, h = blockIdx.y, t0 = blockIdx.x * 64;
    const int bh = b * H_ + h;
    const int lr = ln >> 2, lc = ln & 3;

    // ---- load K (full 512) + Q (64 rows), hi/lo ----
    {
        const __nv_bfloat16* khi = g_khi + (size_t)bh * T_ * 64;
        const __nv_bfloat16* klo = g_klo + (size_t)bh * T_ * 64;
        #pragma unroll
        for (int i = 0; i < 8; ++i) {
            int idx = tid + i * 512;
            int r = idx >> 3, sg = idx & 7;
            asm volatile("cp.async.cg.shared.global [%0], [%1], 16;"
                :: "r"(sb + SM_K + r*KSTR + sg*16), "l"(khi + (size_t)r*64 + sg*8));
        }
        #pragma unroll
        for (int i = 0; i < 8; ++i) {
            int idx = tid + i * 512;
            int r = idx >> 3, sg = idx & 7;
            asm volatile("cp.async.cg.shared.global [%0], [%1], 16;"
                :: "r"(sb + SM_KLO + r*KSTR + sg*16), "l"(klo + (size_t)r*64 + sg*8));
        }
        const __nv_bfloat16* qhi = g_qhi + ((size_t)bh * T_ + t0) * 64;
        const __nv_bfloat16* qlo = g_qlo + ((size_t)bh * T_ + t0) * 64;
        {
            int r = tid >> 3, sg = tid & 7;
            asm volatile("cp.async.cg.shared.global [%0], [%1], 16;"
                :: "r"(sb + SM_Q + r*QSTR + sg*16), "l"(qhi + (size_t)r*64 + sg*8));
            asm volatile("cp.async.cg.shared.global [%0], [%1], 16;"
                :: "r"(sb + SM_QLO + r*QSTR + sg*16), "l"(qlo + (size_t)r*64 + sg*8));
        }
        asm volatile("cp.async.commit_group;");
        asm volatile("cp.async.wait_group 0;");
    }
    __syncthreads();

    // ---- Q fragments ----
    uint32_t aH[4][4], aL[4][4];
    {
        const int row = wm * 16 + lr;
        #pragma unroll
        for (int ks = 0; ks < 4; ++ks) {
            uint32_t off = row * QSTR + ks * 32 + lc * 4;
            aH[ks][0] = lds32(sb + SM_Q + off);
            aH[ks][1] = lds32(sb + SM_Q + off + 8*QSTR);
            aH[ks][2] = lds32(sb + SM_Q + off + 16);
            aH[ks][3] = lds32(sb + SM_Q + off + 8*QSTR + 16);
            aL[ks][0] = lds32(sb + SM_QLO + off);
            aL[ks][1] = lds32(sb + SM_QLO + off + 8*QSTR);
            aL[ks][2] = lds32(sb + SM_QLO + off + 16);
            aL[ks][3] = lds32(sb + SM_QLO + off + 8*QSTR + 16);
        }
    }

    // ---- S = Q K^T ----
    float acc[16][4];
    #pragma unroll
    for (int nt = 0; nt < 16; ++nt) { acc[nt][0]=acc[nt][1]=acc[nt][2]=acc[nt][3]=0.f; }
    #pragma unroll
    for (int nt = 0; nt < 16; ++nt) {
        uint32_t krow = (uint32_t)(wq * 128 + nt * 8 + lr);
        #pragma unroll
        for (int ks = 0; ks < 4; ++ks) {
            uint32_t boff = krow * KSTR + ks * 32 + lc * 4;
            uint32_t bh0 = lds32(sb + SM_K + boff);
            uint32_t bh1 = lds32(sb + SM_K + boff + 16);
            uint32_t bl0 = lds32(sb + SM_KLO + boff);
            uint32_t bl1 = lds32(sb + SM_KLO + boff + 16);
            mma_bf16(acc[nt], aH[ks], bh0, bh1);
            mma_bf16(acc[nt], aH[ks], bl0, bl1);
            mma_bf16(acc[nt], aL[ks], bh0, bh1);
        }
    }

    // ---- softmax over 512 keys ----
    const int row0 = wm * 16 + lr;
    {
        float mx0 = -1e30f, mx1 = -1e30f;
        #pragma unroll
        for (int nt = 0; nt < 16; ++nt) {
            mx0 = fmaxf(mx0, fmaxf(acc[nt][0], acc[nt][1]));
            mx1 = fmaxf(mx1, fmaxf(acc[nt][2], acc[nt][3]));
        }
        mx0 = fmaxf(mx0, __shfl_xor_sync(0xffffffffu, mx0, 1));
        mx0 = fmaxf(mx0, __shfl_xor_sync(0xffffffffu, mx0, 2));
        mx1 = fmaxf(mx1, __shfl_xor_sync(0xffffffffu, mx1, 1));
        mx1 = fmaxf(mx1, __shfl_xor_sync(0xffffffffu, mx1, 2));
        float* exm = (float*)(smem + SM_EXM);
        if (lc == 0) { exm[wq*64 + row0] = mx0; exm[wq*64 + row0 + 8] = mx1; }
        __syncthreads();     // all warps past S MMAs -> K region dead

        // ---- prefetch VT into K region ----
        {
            const __nv_bfloat16* vthi = g_vthi + (size_t)bh * 64 * T_;
            const __nv_bfloat16* vtlo = g_vtlo + (size_t)bh * 64 * T_;
            #pragma unroll
            for (int i = 0; i < 8; ++i) {
                int idx = tid + i * 512;
                int d = idx >> 6, sg = idx & 63;
                asm volatile("cp.async.cg.shared.global [%0], [%1], 16;"
                    :: "r"(sb + SM_VT + d*VTSTR + sg*16), "l"(vthi + (size_t)d*T_ + sg*8));
            }
            #pragma unroll
            for (int i = 0; i < 8; ++i) {
                int idx = tid + i * 512;
                int d = idx >> 6, sg = idx & 63;
                asm volatile("cp.async.cg.shared.global [%0], [%1], 16;"
                    :: "r"(sb + SM_VTLO + d*VTSTR + sg*16), "l"(vtlo + (size_t)d*T_ + sg*8));
            }
            asm volatile("cp.async.commit_group;");
        }

        float m0 = fmaxf(fmaxf(exm[row0],      exm[64+row0]),
                         fmaxf(exm[128+row0],  exm[192+row0]));
        float m1 = fmaxf(fmaxf(exm[row0+8],    exm[64+row0+8]),
                         fmaxf(exm[128+row0+8],exm[192+row0+8]));
        float s0 = 0.f, s1 = 0.f;
        #pragma unroll
        for (int nt = 0; nt < 16; ++nt) {
            acc[nt][0] = __expf(acc[nt][0] - m0); s0 += acc[nt][0];
            acc[nt][1] = __expf(acc[nt][1] - m0); s0 += acc[nt][1];
            acc[nt][2] = __expf(acc[nt][2] - m1); s1 += acc[nt][2];
            acc[nt][3] = __expf(acc[nt][3] - m1); s1 += acc[nt][3];
        }
        s0 += __shfl_xor_sync(0xffffffffu, s0, 1);
        s0 += __shfl_xor_sync(0xffffffffu, s0, 2);
        s1 += __shfl_xor_sync(0xffffffffu, s1, 1);
        s1 += __shfl_xor_sync(0xffffffffu, s1, 2);
        float* exs = (float*)(smem + SM_EXS);
        if (lc == 0) { exs[wq*64 + row0] = s0; exs[wq*64 + row0 + 8] = s1; }
        __syncthreads();
        float inv0 = 1.0f / (exs[row0] + exs[64+row0] + exs[128+row0] + exs[192+row0]);
        float inv1 = 1.0f / (exs[row0+8] + exs[64+row0+8] + exs[128+row0+8] + exs[192+row0+8]);
        #pragma unroll
        for (int nt = 0; nt < 16; ++nt) {
            acc[nt][0] *= inv0; acc[nt][1] *= inv0;
            acc[nt][2] *= inv1; acc[nt][3] *= inv1;
        }
    }

    // ---- wait VT, then PV with probs stores interleaved ----
    asm volatile("cp.async.wait_group 0;");
    __syncthreads();

    float* p0 = probs + ((size_t)bh * T_ + t0 + row0) * 512 + wq*128 + lc*2;
    float* p1 = p0 + (size_t)8 * 512;

    float oacc[8][4];
    #pragma unroll
    for (int dn = 0; dn < 8; ++dn) { oacc[dn][0]=oacc[dn][1]=oacc[dn][2]=oacc[dn][3]=0.f; }
    #pragma unroll
    for (int kk = 0; kk < 8; ++kk) {
        uint32_t phi[4], plo[4];
        phi[0] = pack2(acc[2*kk][0],   acc[2*kk][1]);
        phi[1] = pack2(acc[2*kk][2],   acc[2*kk][3]);
        phi[2] = pack2(acc[2*kk+1][0], acc[2*kk+1][1]);
        phi[3] = pack2(acc[2*kk+1][2], acc[2*kk+1][3]);
        plo[0] = pack2(resid(acc[2*kk][0]),   resid(acc[2*kk][1]));
        plo[1] = pack2(resid(acc[2*kk][2]),   resid(acc[2*kk][3]));
        plo[2] = pack2(resid(acc[2*kk+1][0]), resid(acc[2*kk+1][1]));
        plo[3] = pack2(resid(acc[2*kk+1][2]), resid(acc[2*kk+1][3]));
        // interleaved probs stores (overlap STG with tensor work)
        {
            float2 v00 = {acc[2*kk][0],   acc[2*kk][1]};
            float2 v01 = {acc[2*kk][2],   acc[2*kk][3]};
            float2 v10 = {acc[2*kk+1][0], acc[2*kk+1][1]};
            float2 v11 = {acc[2*kk+1][2], acc[2*kk+1][3]};
            *(float2*)(p0 + (2*kk)*8)   = v00;
            *(float2*)(p1 + (2*kk)*8)   = v01;
            *(float2*)(p0 + (2*kk+1)*8) = v10;
            *(float2*)(p1 + (2*kk+1)*8) = v11;
        }
        uint32_t colV = (uint32_t)((wq*128 + kk*16 + lc*2) * 2);
        #pragma unroll
        for (int dn = 0; dn < 8; ++dn) {
            uint32_t vrow = (uint32_t)(dn*8 + lr);
            uint32_t offH = vrow * VTSTR + colV;
            uint32_t bh0 = lds32(sb + SM_VT + offH);
            uint32_t bh1 = lds32(sb + SM_VT + offH + 16);
            uint32_t bl0 = lds32(sb + SM_VTLO + offH);
            uint32_t bl1 = lds32(sb + SM_VTLO + offH + 16);
            mma_bf16(oacc[dn], phi, bh0, bh1);
            mma_bf16(oacc[dn], phi, bl0, bl1);
            mma_bf16(oacc[dn], plo, bh0, bh1);
        }
    }

    // ---- cross-warp reduce ----
    float* obuf = (float*)(smem + SM_OBUF);
    #pragma unroll
    for (int g = 0; g < 4; ++g) {
        if (wq == g) {
            #pragma unroll
            for (int dn = 0; dn < 8; ++dn) {
                int c = dn*8 + lc*2;
                float* b0 = obuf + row0 * OSTRF + c;
                float* b1 = obuf + (row0 + 8) * OSTRF + c;
                if (g == 0) {
                    b0[0] = oacc[dn][0]; b0[1] = oacc[dn][1];
                    b1[0] = oacc[dn][2]; b1[1] = oacc[dn][3];
                } else {
                    b0[0] += oacc[dn][0]; b0[1] += oacc[dn][1];
                    b1[0] += oacc[dn][2]; b1[1] += oacc[dn][3];
                }
            }
        }
        __syncthreads();
    }

    // ---- write O in combined layout for OUT gemm ----
    {
        int row = tid >> 3, s2 = tid & 7;
        const float* src = obuf + row * OSTRF;
        size_t rb = ((size_t)b * T_ + t0 + row) * 3072 + (size_t)h * 256;
        #pragma unroll
        for (int u = 0; u < 2; ++u) {
            int s = s2 * 2 + u;
            int g = s >> 2, lcx = s & 3;
            int k0 = g * 16 + lcx * 2;
            uint32_t w[4];
            pack_granule(src[k0], src[k0+1], src[k0+8], src[k0+9], w);
            *(uint4*)(g_oc + rb + g*64 + lcx*16) = *(uint4*)w;
        }
    }
}

// --------------------------------- launcher ---------------------------------
extern "C" void kernel_launch(void* const* d_in, const int* in_sizes, int n_in,
                              void* d_out, int out_size)
{
    const float* x     = (const float*)d_in[0];
    const float* Wqkv  = (const float*)d_in[1];
    const float* bqkv  = (const float*)d_in[2];
    const float* Wph   = (const float*)d_in[3];
    const float* bph   = (const float*)d_in[4];
    const float* Wproj = (const float*)d_in[5];
    const float* bproj = (const float*)d_in[6];
    float* out = (float*)d_out;
    float* sa_out = out;
    float* probs  = out + (size_t)BT_*C_;

    uint8_t *xc_p, *wqc_p, *oc_p, *wcc_p;
    float *wcomb_p, *bcomb_p;
    cudaGetSymbolAddress((void**)&xc_p,   g_xc);
    cudaGetSymbolAddress((void**)&wqc_p,  g_wqc);
    cudaGetSymbolAddress((void**)&oc_p,   g_oc);
    cudaGetSymbolAddress((void**)&wcc_p,  g_wcc);
    cudaGetSymbolAddress((void**)&wcomb_p, g_wcomb);
    cudaGetSymbolAddress((void**)&bcomb_p, g_bcomb);

    static int attrs_set = 0;
    if (!attrs_set) {
        cudaFuncSetAttribute(hmma_gemm<0>, cudaFuncAttributeMaxDynamicSharedMemorySize, HM_SMEM);
        cudaFuncSetAttribute(hmma_gemm<1>, cudaFuncAttributeMaxDynamicSharedMemorySize, HM_SMEM);
        cudaFuncSetAttribute(attn_k, cudaFuncAttributeMaxDynamicSharedMemorySize, ATTN_SMEM);
        attrs_set = 1;
    }

    // 1-3: prep on QKV critical path (+ wcomb zero / bcomb init)
    k_prep_xc<<<BT_*192/256, 256>>>(x);
    k_prep_wqc<<<NQKV_*192/256, 256>>>(Wqkv);
    k_binit<<<(C_*C_ + C_ + 255)/256, 256>>>(bproj);

    // 4: QKV GEMM (profiled slot) -> q/k/v bf16 hi/lo
    hmma_gemm<1><<<dim3(NQKV_/128, BT_/128), 256, HM_SMEM>>>(
        xc_p, wqc_p, nullptr, bqkv);

    // 5-7: Wcomb chain (independent of attention)
    k_bcomb<<<288, 256>>>(bph, Wproj);
    sgemm64ks<<<dim3(4, 12, 12), 256>>>(Wph, Wproj, wcomb_p);
    k_prep_wccT<<<C_*192/256, 256>>>();

    // 8: V transpose
    k_vT<<<dim3(T_/64, B_*H_), 256>>>();

    // 9: fused attention -> probs + O(combined)
    attn_k<<<dim3(T_/64, H_, B_), 512, ATTN_SMEM>>>(probs);

    // 10: output GEMM + bcomb -> sa_out
    hmma_gemm<0><<<dim3(C_/128, BT_/128), 256, HM_SMEM>>>(
        oc_p, wcc_p, sa_out, bcomb_p);
}